// round 1
// baseline (speedup 1.0000x reference)
#include <cuda_runtime.h>
#include <math.h>

// Problem constants
namespace {
constexpr int cB   = 2;
constexpr int cS   = 2048;
constexpr int cD   = 1024;
constexpr int cH   = 16;
constexpr int cDK  = 64;     // cD / cH
constexpr int cDFF = 4096;
constexpr int cROWS = cB * cS;          // 4096 token rows
}

// ---------------------------------------------------------------------------
// Static device scratch (allocation-free rule: __device__ globals)
// ---------------------------------------------------------------------------
__device__ float g_xn [(size_t)cROWS * cD];        // LN1 output
__device__ float g_q  [(size_t)cROWS * cD];
__device__ float g_k  [(size_t)cROWS * cD];
__device__ float g_v  [(size_t)cROWS * cD];
__device__ float g_av [(size_t)cROWS * cD];        // attention output (head-sliced layout)
__device__ float g_x1 [(size_t)cROWS * cD];        // x + av@wo^T
__device__ float g_xn2[(size_t)cROWS * cD];        // LN2 output
__device__ float g_h  [(size_t)cROWS * cDFF];      // FFN hidden
__device__ float g_sc [(size_t)cB * cH * cS * cS]; // attention scores / probs (536 MB)

// ---------------------------------------------------------------------------
// LayerNorm: one block per row of 1024, 256 threads, float4 per thread.
// Matches reference: alpha * (x - mean) / (std_unbiased + eps) + bias
// ---------------------------------------------------------------------------
__global__ __launch_bounds__(256) void ln_kernel(
    const float* __restrict__ x, const float* __restrict__ alpha,
    const float* __restrict__ beta, float* __restrict__ y)
{
    const int row = blockIdx.x;
    const int t = threadIdx.x;
    const float4 v = ((const float4*)(x + (size_t)row * cD))[t];

    float s  = v.x + v.y + v.z + v.w;
    float ss = v.x * v.x + v.y * v.y + v.z * v.z + v.w * v.w;
    #pragma unroll
    for (int o = 16; o; o >>= 1) {
        s  += __shfl_xor_sync(0xffffffffu, s, o);
        ss += __shfl_xor_sync(0xffffffffu, ss, o);
    }
    __shared__ float sh_s[8], sh_ss[8];
    if ((t & 31) == 0) { sh_s[t >> 5] = s; sh_ss[t >> 5] = ss; }
    __syncthreads();
    if (t < 32) {
        float s2  = (t < 8) ? sh_s[t]  : 0.f;
        float ss2 = (t < 8) ? sh_ss[t] : 0.f;
        #pragma unroll
        for (int o = 4; o; o >>= 1) {
            s2  += __shfl_xor_sync(0xffffffffu, s2, o);
            ss2 += __shfl_xor_sync(0xffffffffu, ss2, o);
        }
        if (t == 0) { sh_s[0] = s2; sh_ss[0] = ss2; }
    }
    __syncthreads();
    s = sh_s[0]; ss = sh_ss[0];

    const float mean = s * (1.f / (float)cD);
    const float var  = (ss - s * mean) * (1.f / (float)(cD - 1)); // ddof=1
    const float inv  = 1.f / (sqrtf(var) + 1e-6f);                // (std + eps)

    const float4 a = ((const float4*)alpha)[t];
    const float4 b = ((const float4*)beta)[t];
    float4 o;
    o.x = a.x * (v.x - mean) * inv + b.x;
    o.y = a.y * (v.y - mean) * inv + b.y;
    o.z = a.z * (v.z - mean) * inv + b.z;
    o.w = a.w * (v.w - mean) * inv + b.w;
    ((float4*)(y + (size_t)row * cD))[t] = o;
}

// ---------------------------------------------------------------------------
// Fused mask + scale + softmax over rows of length 2048.
// grid.x = B*H*S rows; 256 threads; 8 elements/thread.
// ---------------------------------------------------------------------------
__global__ __launch_bounds__(256) void softmax_kernel(
    float* __restrict__ sc, const int* __restrict__ mask)
{
    const size_t row = blockIdx.x;
    const int b = (int)(row / ((size_t)cH * cS));
    float* p = sc + row * (size_t)cS;
    const int* mrow = mask + (size_t)b * cS;
    const int t = threadIdx.x;

    float vals[8];
    float mx = -1e30f;
    #pragma unroll
    for (int i = 0; i < 2; i++) {
        const float4 v = ((const float4*)p)[t + i * 256];
        const int4  m = ((const int4*)mrow)[t + i * 256];
        const float a0 = m.x ? v.x * 0.125f : -1e9f;  // 1/sqrt(64)=0.125
        const float a1 = m.y ? v.y * 0.125f : -1e9f;
        const float a2 = m.z ? v.z * 0.125f : -1e9f;
        const float a3 = m.w ? v.w * 0.125f : -1e9f;
        vals[i*4+0] = a0; vals[i*4+1] = a1; vals[i*4+2] = a2; vals[i*4+3] = a3;
        mx = fmaxf(mx, fmaxf(fmaxf(a0, a1), fmaxf(a2, a3)));
    }
    #pragma unroll
    for (int o = 16; o; o >>= 1) mx = fmaxf(mx, __shfl_xor_sync(0xffffffffu, mx, o));
    __shared__ float shm[8];
    if ((t & 31) == 0) shm[t >> 5] = mx;
    __syncthreads();
    if (t < 32) {
        float m2 = (t < 8) ? shm[t] : -1e30f;
        #pragma unroll
        for (int o = 4; o; o >>= 1) m2 = fmaxf(m2, __shfl_xor_sync(0xffffffffu, m2, o));
        if (t == 0) shm[0] = m2;
    }
    __syncthreads();
    mx = shm[0];

    float s = 0.f;
    #pragma unroll
    for (int i = 0; i < 8; i++) { vals[i] = __expf(vals[i] - mx); s += vals[i]; }
    #pragma unroll
    for (int o = 16; o; o >>= 1) s += __shfl_xor_sync(0xffffffffu, s, o);
    __shared__ float shs[8];
    if ((t & 31) == 0) shs[t >> 5] = s;
    __syncthreads();
    if (t < 32) {
        float s2 = (t < 8) ? shs[t] : 0.f;
        #pragma unroll
        for (int o = 4; o; o >>= 1) s2 += __shfl_xor_sync(0xffffffffu, s2, o);
        if (t == 0) shs[0] = s2;
    }
    __syncthreads();
    const float inv = 1.f / shs[0];

    #pragma unroll
    for (int i = 0; i < 2; i++) {
        float4 o;
        o.x = vals[i*4+0] * inv; o.y = vals[i*4+1] * inv;
        o.z = vals[i*4+2] * inv; o.w = vals[i*4+3] * inv;
        ((float4*)p)[t + i * 256] = o;
    }
}

// ---------------------------------------------------------------------------
// Tiled SGEMM. NT=true: C[M,N] = A[M,K] * B[N,K]^T (both K-contiguous).
//            NT=false: C[M,N] = A[M,K] * B[K,N]    (B row-major [K,N]).
// Optional batch over blockIdx.z with (b,h) decomposed offsets (attention).
// Exact tiling assumed (all shapes divide evenly).
// ---------------------------------------------------------------------------
template<int BM, int BN, int BK, int TM, int TN, bool NT, bool BIAS, bool RELU, bool RESID>
__global__ __launch_bounds__((BM/TM)*(BN/TN)) void gemm_kernel(
    const float* __restrict__ A, const float* __restrict__ Bm,
    const float* __restrict__ bias, const float* __restrict__ resid,
    float* __restrict__ C, int Kdim,
    int lda, int ldb, int ldc,
    long long sAb, long long sAh, long long sBb, long long sBh,
    long long sCb, long long sCh, int Hdiv)
{
    constexpr int THREADS = (BM/TM)*(BN/TN);
    const int z = blockIdx.z;
    const int zb = z / Hdiv;
    const int zh = z - zb * Hdiv;
    A  += (size_t)zb * sAb + (size_t)zh * sAh;
    Bm += (size_t)zb * sBb + (size_t)zh * sBh;
    C  += (size_t)zb * sCb + (size_t)zh * sCh;

    __shared__ float As[BK][BM + 4];
    __shared__ float Bs[BK][BN + 4];

    const int tid = threadIdx.x;
    const int block_m = blockIdx.y * BM;
    const int block_n = blockIdx.x * BN;
    const int tcol = tid % (BN / TN);
    const int trow = tid / (BN / TN);

    float acc[TM][TN];
    #pragma unroll
    for (int i = 0; i < TM; i++)
        #pragma unroll
        for (int j = 0; j < TN; j++) acc[i][j] = 0.f;

    for (int k0 = 0; k0 < Kdim; k0 += BK) {
        // --- load A tile [BM x BK] (row-major, K-contiguous), transpose into As ---
        constexpr int A_LOADS = (BM * BK) / (THREADS * 4);
        #pragma unroll
        for (int i = 0; i < A_LOADS; i++) {
            const int idx = (tid + i * THREADS) * 4;
            const int r = idx / BK, c = idx % BK;
            const float4 v = *(const float4*)&A[(size_t)(block_m + r) * lda + k0 + c];
            As[c + 0][r] = v.x; As[c + 1][r] = v.y;
            As[c + 2][r] = v.z; As[c + 3][r] = v.w;
        }
        // --- load B tile ---
        constexpr int B_LOADS = (BN * BK) / (THREADS * 4);
        if (NT) {
            #pragma unroll
            for (int i = 0; i < B_LOADS; i++) {
                const int idx = (tid + i * THREADS) * 4;
                const int r = idx / BK, c = idx % BK;
                const float4 v = *(const float4*)&Bm[(size_t)(block_n + r) * ldb + k0 + c];
                Bs[c + 0][r] = v.x; Bs[c + 1][r] = v.y;
                Bs[c + 2][r] = v.z; Bs[c + 3][r] = v.w;
            }
        } else {
            #pragma unroll
            for (int i = 0; i < B_LOADS; i++) {
                const int idx = (tid + i * THREADS) * 4;
                const int r = idx / BN, c = idx % BN;   // r = k, c = n
                const float4 v = *(const float4*)&Bm[(size_t)(k0 + r) * ldb + block_n + c];
                *(float4*)&Bs[r][c] = v;
            }
        }
        __syncthreads();

        #pragma unroll
        for (int kk = 0; kk < BK; kk++) {
            float af[TM], bf[TN];
            #pragma unroll
            for (int i4 = 0; i4 < TM / 4; i4++) {
                const float4 a = *(const float4*)&As[kk][trow * TM + i4 * 4];
                af[i4*4+0] = a.x; af[i4*4+1] = a.y; af[i4*4+2] = a.z; af[i4*4+3] = a.w;
            }
            #pragma unroll
            for (int j4 = 0; j4 < TN / 4; j4++) {
                const float4 b = *(const float4*)&Bs[kk][tcol * TN + j4 * 4];
                bf[j4*4+0] = b.x; bf[j4*4+1] = b.y; bf[j4*4+2] = b.z; bf[j4*4+3] = b.w;
            }
            #pragma unroll
            for (int i = 0; i < TM; i++)
                #pragma unroll
                for (int j = 0; j < TN; j++)
                    acc[i][j] += af[i] * bf[j];
        }
        __syncthreads();
    }

    // --- epilogue (float4 stores, optional bias / relu / residual) ---
    #pragma unroll
    for (int i = 0; i < TM; i++) {
        const int row = block_m + trow * TM + i;
        float* crow = C + (size_t)row * ldc + block_n + tcol * TN;
        const float* rrow = RESID ? (resid + (size_t)row * ldc + block_n + tcol * TN) : nullptr;
        #pragma unroll
        for (int j4 = 0; j4 < TN / 4; j4++) {
            float4 o;
            o.x = acc[i][j4*4+0]; o.y = acc[i][j4*4+1];
            o.z = acc[i][j4*4+2]; o.w = acc[i][j4*4+3];
            if (BIAS) {
                const float4 bb = *(const float4*)&bias[block_n + tcol * TN + j4 * 4];
                o.x += bb.x; o.y += bb.y; o.z += bb.z; o.w += bb.w;
            }
            if (RELU) {
                o.x = fmaxf(o.x, 0.f); o.y = fmaxf(o.y, 0.f);
                o.z = fmaxf(o.z, 0.f); o.w = fmaxf(o.w, 0.f);
            }
            if (RESID) {
                const float4 rr = *(const float4*)&rrow[j4 * 4];
                o.x += rr.x; o.y += rr.y; o.z += rr.z; o.w += rr.w;
            }
            *(float4*)&crow[j4 * 4] = o;
        }
    }
}

// ---------------------------------------------------------------------------
// Host-side launch pipeline (graph-capturable: kernel launches only)
// ---------------------------------------------------------------------------
extern "C" void kernel_launch(void* const* d_in, const int* in_sizes, int n_in,
                              void* d_out, int out_size)
{
    const float* x      = (const float*)d_in[0];
    const int*   mask   = (const int*)  d_in[1];
    const float* wq     = (const float*)d_in[2];
    const float* wk     = (const float*)d_in[3];
    const float* wv     = (const float*)d_in[4];
    const float* wo     = (const float*)d_in[5];
    const float* w1     = (const float*)d_in[6];
    const float* b1     = (const float*)d_in[7];
    const float* w2     = (const float*)d_in[8];
    const float* b2     = (const float*)d_in[9];
    const float* alpha1 = (const float*)d_in[10];
    const float* bias1  = (const float*)d_in[11];
    const float* alpha2 = (const float*)d_in[12];
    const float* bias2  = (const float*)d_in[13];
    float* out = (float*)d_out;

    float *xn, *q, *k, *v, *av, *x1, *xn2, *hb, *sc;
    cudaGetSymbolAddress((void**)&xn,  g_xn);
    cudaGetSymbolAddress((void**)&q,   g_q);
    cudaGetSymbolAddress((void**)&k,   g_k);
    cudaGetSymbolAddress((void**)&v,   g_v);
    cudaGetSymbolAddress((void**)&av,  g_av);
    cudaGetSymbolAddress((void**)&x1,  g_x1);
    cudaGetSymbolAddress((void**)&xn2, g_xn2);
    cudaGetSymbolAddress((void**)&hb,  g_h);
    cudaGetSymbolAddress((void**)&sc,  g_sc);

    const long long SD  = (long long)cS * cD;          // token-batch stride
    const long long SS  = (long long)cS * cS;          // per-head score stride
    const long long HSS = (long long)cH * SS;          // per-batch score stride

    // 1) LN1: xn = LN(x)
    ln_kernel<<<cROWS, 256>>>(x, alpha1, bias1, xn);

    // 2-4) Q/K/V projections: [4096,1024] x [1024,1024]^T
    {
        dim3 grid(cD / 128, cROWS / 128, 1);
        gemm_kernel<128,128,16,8,8,true,false,false,false><<<grid, 256>>>(
            xn, wq, nullptr, nullptr, q, cD, cD, cD, cD, 0,0,0,0,0,0, 1);
        gemm_kernel<128,128,16,8,8,true,false,false,false><<<grid, 256>>>(
            xn, wk, nullptr, nullptr, k, cD, cD, cD, cD, 0,0,0,0,0,0, 1);
        gemm_kernel<128,128,16,8,8,true,false,false,false><<<grid, 256>>>(
            xn, wv, nullptr, nullptr, v, cD, cD, cD, cD, 0,0,0,0,0,0, 1);
    }

    // 5) Scores: per (b,h): S[2048,2048] = Qh[2048,64] * Kh[2048,64]^T
    {
        dim3 grid(cS / 128, cS / 128, cB * cH);
        gemm_kernel<128,128,16,8,8,true,false,false,false><<<grid, 256>>>(
            q, k, nullptr, nullptr, sc, cDK, cD, cD, cS,
            SD, cDK, SD, cDK, HSS, SS, cH);
    }

    // 6) mask + scale + softmax (in place)
    softmax_kernel<<<cB * cH * cS, 256>>>(sc, mask);

    // 7) AV: per (b,h): av[2048,64] = P[2048,2048] * Vh[2048,64]  (NN)
    {
        dim3 grid(cDK / 64, cS / 128, cB * cH);
        gemm_kernel<128,64,16,8,4,false,false,false,false><<<grid, 256>>>(
            sc, v, nullptr, nullptr, av, cS, cS, cD, cD,
            HSS, SS, SD, cDK, SD, cDK, cH);
    }

    // 8) WO projection + residual: x1 = x + av @ wo^T
    {
        dim3 grid(cD / 128, cROWS / 128, 1);
        gemm_kernel<128,128,16,8,8,true,false,false,true><<<grid, 256>>>(
            av, wo, nullptr, x, x1, cD, cD, cD, cD, 0,0,0,0,0,0, 1);
    }

    // 9) LN2
    ln_kernel<<<cROWS, 256>>>(x1, alpha2, bias2, xn2);

    // 10) FFN1: h = relu(xn2 @ w1^T + b1)  [4096,4096]
    {
        dim3 grid(cDFF / 128, cROWS / 128, 1);
        gemm_kernel<128,128,16,8,8,true,true,true,false><<<grid, 256>>>(
            xn2, w1, b1, nullptr, hb, cD, cD, cD, cDFF, 0,0,0,0,0,0, 1);
    }

    // 11) FFN2: out = x1 + h @ w2^T + b2  [4096,1024]
    {
        dim3 grid(cD / 128, cROWS / 128, 1);
        gemm_kernel<128,128,16,8,8,true,true,false,true><<<grid, 256>>>(
            hb, w2, b2, x1, out, cDFF, cDFF, cDFF, cD, 0,0,0,0,0,0, 1);
    }
    (void)in_sizes; (void)n_in; (void)out_size;
}

// round 3
// speedup vs baseline: 1.5814x; 1.5814x over previous
#include <cuda_runtime.h>
#include <math.h>
#include <stdint.h>

// Problem constants
namespace {
constexpr int cB   = 2;
constexpr int cS   = 2048;
constexpr int cD   = 1024;
constexpr int cH   = 16;
constexpr int cDK  = 64;     // cD / cH
constexpr int cDFF = 4096;
constexpr int cROWS = cB * cS;          // 4096 token rows
}

// ---------------------------------------------------------------------------
// Static device scratch (allocation-free rule: __device__ globals)
// ---------------------------------------------------------------------------
__device__ float g_xn [(size_t)cROWS * cD];        // LN1 output
__device__ float g_q  [(size_t)cROWS * cD];
__device__ float g_k  [(size_t)cROWS * cD];
__device__ float g_v  [(size_t)cROWS * cD];
__device__ float g_av [(size_t)cROWS * cD];        // attention output (head-sliced layout)
__device__ float g_x1 [(size_t)cROWS * cD];        // x + av@wo^T
__device__ float g_xn2[(size_t)cROWS * cD];        // LN2 output
__device__ float g_h  [(size_t)cROWS * cDFF];      // FFN hidden
__device__ float g_sc [(size_t)cB * cH * cS * cS]; // attention scores / probs (536 MB)

// ---------------------------------------------------------------------------
// Helpers
// ---------------------------------------------------------------------------
__device__ __forceinline__ float to_tf32(float x) {
    uint32_t u;
    asm("cvt.rna.tf32.f32 %0, %1;" : "=r"(u) : "f"(x));
    return __uint_as_float(u);
}

__device__ __forceinline__ void mma_tf32(float* c, const uint32_t* a, const uint32_t* b) {
    asm volatile(
        "mma.sync.aligned.m16n8k8.row.col.f32.tf32.tf32.f32 "
        "{%0,%1,%2,%3}, {%4,%5,%6,%7}, {%8,%9}, {%0,%1,%2,%3};\n"
        : "+f"(c[0]), "+f"(c[1]), "+f"(c[2]), "+f"(c[3])
        : "r"(a[0]), "r"(a[1]), "r"(a[2]), "r"(a[3]), "r"(b[0]), "r"(b[1]));
}

// ---------------------------------------------------------------------------
// LayerNorm: one block per row of 1024, 256 threads, float4 per thread.
// Matches reference: alpha * (x - mean) / (std_unbiased + eps) + bias
// ---------------------------------------------------------------------------
__global__ __launch_bounds__(256) void ln_kernel(
    const float* __restrict__ x, const float* __restrict__ alpha,
    const float* __restrict__ beta, float* __restrict__ y)
{
    const int row = blockIdx.x;
    const int t = threadIdx.x;
    const float4 v = ((const float4*)(x + (size_t)row * cD))[t];

    float s  = v.x + v.y + v.z + v.w;
    float ss = v.x * v.x + v.y * v.y + v.z * v.z + v.w * v.w;
    #pragma unroll
    for (int o = 16; o; o >>= 1) {
        s  += __shfl_xor_sync(0xffffffffu, s, o);
        ss += __shfl_xor_sync(0xffffffffu, ss, o);
    }
    __shared__ float sh_s[8], sh_ss[8];
    if ((t & 31) == 0) { sh_s[t >> 5] = s; sh_ss[t >> 5] = ss; }
    __syncthreads();
    if (t < 32) {
        float s2  = (t < 8) ? sh_s[t]  : 0.f;
        float ss2 = (t < 8) ? sh_ss[t] : 0.f;
        #pragma unroll
        for (int o = 4; o; o >>= 1) {
            s2  += __shfl_xor_sync(0xffffffffu, s2, o);
            ss2 += __shfl_xor_sync(0xffffffffu, ss2, o);
        }
        if (t == 0) { sh_s[0] = s2; sh_ss[0] = ss2; }
    }
    __syncthreads();
    s = sh_s[0]; ss = sh_ss[0];

    const float mean = s * (1.f / (float)cD);
    const float var  = (ss - s * mean) * (1.f / (float)(cD - 1)); // ddof=1
    const float inv  = 1.f / (sqrtf(var) + 1e-6f);                // (std + eps)

    const float4 a = ((const float4*)alpha)[t];
    const float4 b = ((const float4*)beta)[t];
    float4 o;
    o.x = a.x * (v.x - mean) * inv + b.x;
    o.y = a.y * (v.y - mean) * inv + b.y;
    o.z = a.z * (v.z - mean) * inv + b.z;
    o.w = a.w * (v.w - mean) * inv + b.w;
    ((float4*)(y + (size_t)row * cD))[t] = o;
}

// ---------------------------------------------------------------------------
// Fused mask + scale + softmax over rows of length 2048.
// ---------------------------------------------------------------------------
__global__ __launch_bounds__(256) void softmax_kernel(
    float* __restrict__ sc, const int* __restrict__ mask)
{
    const size_t row = blockIdx.x;
    const int b = (int)(row / ((size_t)cH * cS));
    float* p = sc + row * (size_t)cS;
    const int* mrow = mask + (size_t)b * cS;
    const int t = threadIdx.x;

    float vals[8];
    float mx = -1e30f;
    #pragma unroll
    for (int i = 0; i < 2; i++) {
        const float4 v = ((const float4*)p)[t + i * 256];
        const int4  m = ((const int4*)mrow)[t + i * 256];
        const float a0 = m.x ? v.x * 0.125f : -1e9f;  // 1/sqrt(64)=0.125
        const float a1 = m.y ? v.y * 0.125f : -1e9f;
        const float a2 = m.z ? v.z * 0.125f : -1e9f;
        const float a3 = m.w ? v.w * 0.125f : -1e9f;
        vals[i*4+0] = a0; vals[i*4+1] = a1; vals[i*4+2] = a2; vals[i*4+3] = a3;
        mx = fmaxf(mx, fmaxf(fmaxf(a0, a1), fmaxf(a2, a3)));
    }
    #pragma unroll
    for (int o = 16; o; o >>= 1) mx = fmaxf(mx, __shfl_xor_sync(0xffffffffu, mx, o));
    __shared__ float shm[8];
    if ((t & 31) == 0) shm[t >> 5] = mx;
    __syncthreads();
    if (t < 32) {
        float m2 = (t < 8) ? shm[t] : -1e30f;
        #pragma unroll
        for (int o = 4; o; o >>= 1) m2 = fmaxf(m2, __shfl_xor_sync(0xffffffffu, m2, o));
        if (t == 0) shm[0] = m2;
    }
    __syncthreads();
    mx = shm[0];

    float s = 0.f;
    #pragma unroll
    for (int i = 0; i < 8; i++) { vals[i] = __expf(vals[i] - mx); s += vals[i]; }
    #pragma unroll
    for (int o = 16; o; o >>= 1) s += __shfl_xor_sync(0xffffffffu, s, o);
    __shared__ float shs[8];
    if ((t & 31) == 0) shs[t >> 5] = s;
    __syncthreads();
    if (t < 32) {
        float s2 = (t < 8) ? shs[t] : 0.f;
        #pragma unroll
        for (int o = 4; o; o >>= 1) s2 += __shfl_xor_sync(0xffffffffu, s2, o);
        if (t == 0) shs[0] = s2;
    }
    __syncthreads();
    const float inv = 1.f / shs[0];

    #pragma unroll
    for (int i = 0; i < 2; i++) {
        float4 o;
        o.x = vals[i*4+0] * inv; o.y = vals[i*4+1] * inv;
        o.z = vals[i*4+2] * inv; o.w = vals[i*4+3] * inv;
        ((float4*)p)[t + i * 256] = o;
    }
}

// ---------------------------------------------------------------------------
// TF32 tensor-core GEMM (mma.sync m16n8k8).
// NT=true:  C[M,N] = A[M,K] * B[N,K]^T   (both K-contiguous)
// NT=false: C[M,N] = A[M,K] * B[K,N]     (B row-major [K,N])
// Shared layout: As[k][m], Bs[k][n], pad 8 floats (stride%32==8 ->
// the 4 tg-groups of each fragment hit disjoint bank ranges).
// Batch over blockIdx.z with (b,h) decomposed offsets.
// ---------------------------------------------------------------------------
template<int BM, int BN, int BK, int WM, int WN, bool NT, bool BIAS, bool RELU, bool RESID>
__global__ __launch_bounds__((BM/WM)*(BN/WN)*32) void mma_gemm_kernel(
    const float* __restrict__ A, const float* __restrict__ Bm,
    const float* __restrict__ bias, const float* __restrict__ resid,
    float* __restrict__ C, int Kdim,
    int lda, int ldb, int ldc,
    long long sAb, long long sAh, long long sBb, long long sBh,
    long long sCb, long long sCh, int Hdiv)
{
    constexpr int WARPS_M = BM / WM;
    constexpr int WARPS_N = BN / WN;
    constexpr int THREADS = WARPS_M * WARPS_N * 32;
    constexpr int MT  = WM / 16;   // m16 tiles per warp
    constexpr int NTL = WN / 8;    // n8 tiles per warp
    constexpr int KS  = BK / 8;    // k8 steps per smem tile
    constexpr int PAD = 8;

    const int z = blockIdx.z;
    const int zb = z / Hdiv;
    const int zh = z - zb * Hdiv;
    A  += (size_t)zb * sAb + (size_t)zh * sAh;
    Bm += (size_t)zb * sBb + (size_t)zh * sBh;
    C  += (size_t)zb * sCb + (size_t)zh * sCh;

    __shared__ float As[BK][BM + PAD];
    __shared__ float Bs[BK][BN + PAD];

    const int tid  = threadIdx.x;
    const int warp = tid >> 5;
    const int lane = tid & 31;
    const int g  = lane >> 2;   // group id (0..7)
    const int tg = lane & 3;    // thread in group (0..3)
    const int warp_m = warp / WARPS_N;
    const int warp_n = warp % WARPS_N;

    const int block_m = blockIdx.y * BM;
    const int block_n = blockIdx.x * BN;

    float acc[MT][NTL][4];
    #pragma unroll
    for (int i = 0; i < MT; i++)
        #pragma unroll
        for (int j = 0; j < NTL; j++)
            #pragma unroll
            for (int r = 0; r < 4; r++) acc[i][j][r] = 0.f;

    for (int k0 = 0; k0 < Kdim; k0 += BK) {
        // --- A tile [BM x BK] row-major -> As[k][m] (tf32-rounded) ---
        constexpr int A_ITERS = (BM * BK) / (THREADS * 4);
        #pragma unroll
        for (int i = 0; i < A_ITERS; i++) {
            const int idx = (tid + i * THREADS) * 4;
            const int r = idx / BK, c = idx % BK;
            const float4 v = *(const float4*)&A[(size_t)(block_m + r) * lda + k0 + c];
            As[c + 0][r] = to_tf32(v.x); As[c + 1][r] = to_tf32(v.y);
            As[c + 2][r] = to_tf32(v.z); As[c + 3][r] = to_tf32(v.w);
        }
        // --- B tile -> Bs[k][n] ---
        constexpr int B_ITERS = (BN * BK) / (THREADS * 4);
        if (NT) {
            #pragma unroll
            for (int i = 0; i < B_ITERS; i++) {
                const int idx = (tid + i * THREADS) * 4;
                const int r = idx / BK, c = idx % BK;
                const float4 v = *(const float4*)&Bm[(size_t)(block_n + r) * ldb + k0 + c];
                Bs[c + 0][r] = to_tf32(v.x); Bs[c + 1][r] = to_tf32(v.y);
                Bs[c + 2][r] = to_tf32(v.z); Bs[c + 3][r] = to_tf32(v.w);
            }
        } else {
            #pragma unroll
            for (int i = 0; i < B_ITERS; i++) {
                const int idx = (tid + i * THREADS) * 4;
                const int r = idx / BN, c = idx % BN;   // r = k, c = n
                const float4 v = *(const float4*)&Bm[(size_t)(k0 + r) * ldb + block_n + c];
                float4 o;
                o.x = to_tf32(v.x); o.y = to_tf32(v.y);
                o.z = to_tf32(v.z); o.w = to_tf32(v.w);
                *(float4*)&Bs[r][c] = o;
            }
        }
        __syncthreads();

        #pragma unroll
        for (int ks = 0; ks < KS; ks++) {
            const int kb = ks * 8;
            uint32_t af[MT][4];
            uint32_t bf[NTL][2];
            #pragma unroll
            for (int mt = 0; mt < MT; mt++) {
                const int mb = warp_m * WM + mt * 16 + g;
                af[mt][0] = __float_as_uint(As[kb + tg    ][mb    ]);
                af[mt][1] = __float_as_uint(As[kb + tg    ][mb + 8]);
                af[mt][2] = __float_as_uint(As[kb + tg + 4][mb    ]);
                af[mt][3] = __float_as_uint(As[kb + tg + 4][mb + 8]);
            }
            #pragma unroll
            for (int nt = 0; nt < NTL; nt++) {
                const int nb = warp_n * WN + nt * 8 + g;
                bf[nt][0] = __float_as_uint(Bs[kb + tg    ][nb]);
                bf[nt][1] = __float_as_uint(Bs[kb + tg + 4][nb]);
            }
            #pragma unroll
            for (int mt = 0; mt < MT; mt++)
                #pragma unroll
                for (int nt = 0; nt < NTL; nt++)
                    mma_tf32(acc[mt][nt], af[mt], bf[nt]);
        }
        __syncthreads();
    }

    // --- epilogue: float2 stores, optional bias / relu / residual ---
    #pragma unroll
    for (int mt = 0; mt < MT; mt++) {
        const int row0 = block_m + warp_m * WM + mt * 16 + g;
        #pragma unroll
        for (int nt = 0; nt < NTL; nt++) {
            const int col = block_n + warp_n * WN + nt * 8 + 2 * tg;
            float2 lo = make_float2(acc[mt][nt][0], acc[mt][nt][1]);
            float2 hi = make_float2(acc[mt][nt][2], acc[mt][nt][3]);
            if (BIAS) {
                const float2 bb = *(const float2*)&bias[col];
                lo.x += bb.x; lo.y += bb.y; hi.x += bb.x; hi.y += bb.y;
            }
            if (RELU) {
                lo.x = fmaxf(lo.x, 0.f); lo.y = fmaxf(lo.y, 0.f);
                hi.x = fmaxf(hi.x, 0.f); hi.y = fmaxf(hi.y, 0.f);
            }
            if (RESID) {
                const float2 r0 = *(const float2*)&resid[(size_t)row0 * ldc + col];
                const float2 r1 = *(const float2*)&resid[(size_t)(row0 + 8) * ldc + col];
                lo.x += r0.x; lo.y += r0.y; hi.x += r1.x; hi.y += r1.y;
            }
            *(float2*)&C[(size_t)row0 * ldc + col]       = lo;
            *(float2*)&C[(size_t)(row0 + 8) * ldc + col] = hi;
        }
    }
}

// ---------------------------------------------------------------------------
// Host-side launch pipeline (graph-capturable: kernel launches only)
// ---------------------------------------------------------------------------
extern "C" void kernel_launch(void* const* d_in, const int* in_sizes, int n_in,
                              void* d_out, int out_size)
{
    const float* x      = (const float*)d_in[0];
    const int*   mask   = (const int*)  d_in[1];
    const float* wq     = (const float*)d_in[2];
    const float* wk     = (const float*)d_in[3];
    const float* wv     = (const float*)d_in[4];
    const float* wo     = (const float*)d_in[5];
    const float* w1     = (const float*)d_in[6];
    const float* b1     = (const float*)d_in[7];
    const float* w2     = (const float*)d_in[8];
    const float* b2     = (const float*)d_in[9];
    const float* alpha1 = (const float*)d_in[10];
    const float* bias1  = (const float*)d_in[11];
    const float* alpha2 = (const float*)d_in[12];
    const float* bias2  = (const float*)d_in[13];
    float* out = (float*)d_out;

    float *xn, *q, *k, *v, *av, *x1, *xn2, *hb, *sc;
    cudaGetSymbolAddress((void**)&xn,  g_xn);
    cudaGetSymbolAddress((void**)&q,   g_q);
    cudaGetSymbolAddress((void**)&k,   g_k);
    cudaGetSymbolAddress((void**)&v,   g_v);
    cudaGetSymbolAddress((void**)&av,  g_av);
    cudaGetSymbolAddress((void**)&x1,  g_x1);
    cudaGetSymbolAddress((void**)&xn2, g_xn2);
    cudaGetSymbolAddress((void**)&hb,  g_h);
    cudaGetSymbolAddress((void**)&sc,  g_sc);

    const long long SD  = (long long)cS * cD;          // token-batch stride
    const long long SS  = (long long)cS * cS;          // per-head score stride
    const long long HSS = (long long)cH * SS;          // per-batch score stride

    // 1) LN1: xn = LN(x)
    ln_kernel<<<cROWS, 256>>>(x, alpha1, bias1, xn);

    // 2-4) Q/K/V projections: [4096,1024] x [1024,1024]^T
    {
        dim3 grid(cD / 128, cROWS / 128, 1);
        mma_gemm_kernel<128,128,32,64,32,true,false,false,false><<<grid, 256>>>(
            xn, wq, nullptr, nullptr, q, cD, cD, cD, cD, 0,0,0,0,0,0, 1);
        mma_gemm_kernel<128,128,32,64,32,true,false,false,false><<<grid, 256>>>(
            xn, wk, nullptr, nullptr, k, cD, cD, cD, cD, 0,0,0,0,0,0, 1);
        mma_gemm_kernel<128,128,32,64,32,true,false,false,false><<<grid, 256>>>(
            xn, wv, nullptr, nullptr, v, cD, cD, cD, cD, 0,0,0,0,0,0, 1);
    }

    // 5) Scores: per (b,h): S[2048,2048] = Qh[2048,64] * Kh[2048,64]^T
    {
        dim3 grid(cS / 128, cS / 128, cB * cH);
        mma_gemm_kernel<128,128,32,64,32,true,false,false,false><<<grid, 256>>>(
            q, k, nullptr, nullptr, sc, cDK, cD, cD, cS,
            SD, cDK, SD, cDK, HSS, SS, cH);
    }

    // 6) mask + scale + softmax (in place)
    softmax_kernel<<<cB * cH * cS, 256>>>(sc, mask);

    // 7) AV: per (b,h): av[2048,64] = P[2048,2048] * Vh[2048,64]  (NN)
    {
        dim3 grid(1, cS / 128, cB * cH);
        mma_gemm_kernel<128,64,32,64,32,false,false,false,false><<<grid, 128>>>(
            sc, v, nullptr, nullptr, av, cS, cS, cD, cD,
            HSS, SS, SD, cDK, SD, cDK, cH);
    }

    // 8) WO projection + residual: x1 = x + av @ wo^T
    {
        dim3 grid(cD / 128, cROWS / 128, 1);
        mma_gemm_kernel<128,128,32,64,32,true,false,false,true><<<grid, 256>>>(
            av, wo, nullptr, x, x1, cD, cD, cD, cD, 0,0,0,0,0,0, 1);
    }

    // 9) LN2
    ln_kernel<<<cROWS, 256>>>(x1, alpha2, bias2, xn2);

    // 10) FFN1: h = relu(xn2 @ w1^T + b1)  [4096,4096]
    {
        dim3 grid(cDFF / 128, cROWS / 128, 1);
        mma_gemm_kernel<128,128,32,64,32,true,true,true,false><<<grid, 256>>>(
            xn2, w1, b1, nullptr, hb, cD, cD, cD, cDFF, 0,0,0,0,0,0, 1);
    }

    // 11) FFN2: out = x1 + h @ w2^T + b2  [4096,1024]
    {
        dim3 grid(cD / 128, cROWS / 128, 1);
        mma_gemm_kernel<128,128,32,64,32,true,true,false,true><<<grid, 256>>>(
            hb, w2, b2, x1, out, cDFF, cDFF, cDFF, cD, 0,0,0,0,0,0, 1);
    }
    (void)in_sizes; (void)n_in; (void)out_size;
}

// round 5
// speedup vs baseline: 2.6094x; 1.6501x over previous
#include <cuda_runtime.h>
#include <math.h>
#include <stdint.h>

// Problem constants
namespace {
constexpr int cB   = 2;
constexpr int cS   = 2048;
constexpr int cD   = 1024;
constexpr int cH   = 16;
constexpr int cDK  = 64;     // cD / cH
constexpr int cDFF = 4096;
constexpr int cROWS = cB * cS;          // 4096 token rows
}

// ---------------------------------------------------------------------------
// Static device scratch (allocation-free rule: __device__ globals)
// ---------------------------------------------------------------------------
__device__ float g_xn [(size_t)cROWS * cD];        // LN1 output (tf32-rounded)
__device__ float g_q  [(size_t)cROWS * cD];
__device__ float g_k  [(size_t)cROWS * cD];
__device__ float g_v  [(size_t)cROWS * cD];
__device__ float g_av [(size_t)cROWS * cD];
__device__ float g_x1 [(size_t)cROWS * cD];        // x + av@wo^T (full fp32)
__device__ float g_xn2[(size_t)cROWS * cD];        // LN2 output (tf32-rounded)
__device__ float g_h  [(size_t)cROWS * cDFF];      // FFN hidden (tf32-rounded)
__device__ float g_sc [(size_t)cB * cH * cS * cS]; // scores / probs (536 MB)
// tf32-rounded weight copies
__device__ float g_wqr[(size_t)cD * cD];
__device__ float g_wkr[(size_t)cD * cD];
__device__ float g_wvr[(size_t)cD * cD];
__device__ float g_wor[(size_t)cD * cD];
__device__ float g_w1r[(size_t)cDFF * cD];
__device__ float g_w2r[(size_t)cD * cDFF];

// ---------------------------------------------------------------------------
// Helpers
// ---------------------------------------------------------------------------
__device__ __forceinline__ float to_tf32(float x) {
    uint32_t u;
    asm("cvt.rna.tf32.f32 %0, %1;" : "=r"(u) : "f"(x));
    return __uint_as_float(u);
}

__device__ __forceinline__ void mma_tf32(float* c, const uint32_t* a, const uint32_t* b) {
    asm volatile(
        "mma.sync.aligned.m16n8k8.row.col.f32.tf32.tf32.f32 "
        "{%0,%1,%2,%3}, {%4,%5,%6,%7}, {%8,%9}, {%0,%1,%2,%3};\n"
        : "+f"(c[0]), "+f"(c[1]), "+f"(c[2]), "+f"(c[3])
        : "r"(a[0]), "r"(a[1]), "r"(a[2]), "r"(a[3]), "r"(b[0]), "r"(b[1]));
}

__device__ __forceinline__ void cp16(uint32_t s, const void* g) {
    asm volatile("cp.async.cg.shared.global [%0], [%1], 16;\n" :: "r"(s), "l"(g));
}
__device__ __forceinline__ void cp_commit() {
    asm volatile("cp.async.commit_group;\n");
}
template<int N> __device__ __forceinline__ void cp_wait() {
    asm volatile("cp.async.wait_group %0;\n" :: "n"(N));
}

// ---------------------------------------------------------------------------
// Elementwise round-to-tf32 (for weight matrices), float4 vectorized.
// ---------------------------------------------------------------------------
__global__ __launch_bounds__(256) void round_tf32_kernel(
    const float4* __restrict__ in, float4* __restrict__ out, int n4)
{
    const int i = blockIdx.x * blockDim.x + threadIdx.x;
    if (i < n4) {
        float4 v = in[i];
        v.x = to_tf32(v.x); v.y = to_tf32(v.y);
        v.z = to_tf32(v.z); v.w = to_tf32(v.w);
        out[i] = v;
    }
}

// ---------------------------------------------------------------------------
// LayerNorm: one block per row of 1024, 256 threads, float4 per thread.
// Matches reference: alpha * (x - mean) / (std_unbiased + eps) + bias
// Output is tf32-rounded (it is only ever consumed as a GEMM operand).
// ---------------------------------------------------------------------------
__global__ __launch_bounds__(256) void ln_kernel(
    const float* __restrict__ x, const float* __restrict__ alpha,
    const float* __restrict__ beta, float* __restrict__ y)
{
    const int row = blockIdx.x;
    const int t = threadIdx.x;
    const float4 v = ((const float4*)(x + (size_t)row * cD))[t];

    float s  = v.x + v.y + v.z + v.w;
    float ss = v.x * v.x + v.y * v.y + v.z * v.z + v.w * v.w;
    #pragma unroll
    for (int o = 16; o; o >>= 1) {
        s  += __shfl_xor_sync(0xffffffffu, s, o);
        ss += __shfl_xor_sync(0xffffffffu, ss, o);
    }
    __shared__ float sh_s[8], sh_ss[8];
    if ((t & 31) == 0) { sh_s[t >> 5] = s; sh_ss[t >> 5] = ss; }
    __syncthreads();
    if (t < 32) {
        float s2  = (t < 8) ? sh_s[t]  : 0.f;
        float ss2 = (t < 8) ? sh_ss[t] : 0.f;
        #pragma unroll
        for (int o = 4; o; o >>= 1) {
            s2  += __shfl_xor_sync(0xffffffffu, s2, o);
            ss2 += __shfl_xor_sync(0xffffffffu, ss2, o);
        }
        if (t == 0) { sh_s[0] = s2; sh_ss[0] = ss2; }
    }
    __syncthreads();
    s = sh_s[0]; ss = sh_ss[0];

    const float mean = s * (1.f / (float)cD);
    const float var  = (ss - s * mean) * (1.f / (float)(cD - 1)); // ddof=1
    const float inv  = 1.f / (sqrtf(var) + 1e-6f);                // (std + eps)

    const float4 a = ((const float4*)alpha)[t];
    const float4 b = ((const float4*)beta)[t];
    float4 o;
    o.x = to_tf32(a.x * (v.x - mean) * inv + b.x);
    o.y = to_tf32(a.y * (v.y - mean) * inv + b.y);
    o.z = to_tf32(a.z * (v.z - mean) * inv + b.z);
    o.w = to_tf32(a.w * (v.w - mean) * inv + b.w);
    ((float4*)(y + (size_t)row * cD))[t] = o;
}

// ---------------------------------------------------------------------------
// Fused mask + scale + softmax over rows of length 2048 (output tf32-rounded).
// ---------------------------------------------------------------------------
__global__ __launch_bounds__(256) void softmax_kernel(
    float* __restrict__ sc, const int* __restrict__ mask)
{
    const size_t row = blockIdx.x;
    const int b = (int)(row / ((size_t)cH * cS));
    float* p = sc + row * (size_t)cS;
    const int* mrow = mask + (size_t)b * cS;
    const int t = threadIdx.x;

    float vals[8];
    float mx = -1e30f;
    #pragma unroll
    for (int i = 0; i < 2; i++) {
        const float4 v = ((const float4*)p)[t + i * 256];
        const int4  m = ((const int4*)mrow)[t + i * 256];
        const float a0 = m.x ? v.x * 0.125f : -1e9f;  // 1/sqrt(64)=0.125
        const float a1 = m.y ? v.y * 0.125f : -1e9f;
        const float a2 = m.z ? v.z * 0.125f : -1e9f;
        const float a3 = m.w ? v.w * 0.125f : -1e9f;
        vals[i*4+0] = a0; vals[i*4+1] = a1; vals[i*4+2] = a2; vals[i*4+3] = a3;
        mx = fmaxf(mx, fmaxf(fmaxf(a0, a1), fmaxf(a2, a3)));
    }
    #pragma unroll
    for (int o = 16; o; o >>= 1) mx = fmaxf(mx, __shfl_xor_sync(0xffffffffu, mx, o));
    __shared__ float shm[8];
    if ((t & 31) == 0) shm[t >> 5] = mx;
    __syncthreads();
    if (t < 32) {
        float m2 = (t < 8) ? shm[t] : -1e30f;
        #pragma unroll
        for (int o = 4; o; o >>= 1) m2 = fmaxf(m2, __shfl_xor_sync(0xffffffffu, m2, o));
        if (t == 0) shm[0] = m2;
    }
    __syncthreads();
    mx = shm[0];

    float s = 0.f;
    #pragma unroll
    for (int i = 0; i < 8; i++) { vals[i] = __expf(vals[i] - mx); s += vals[i]; }
    #pragma unroll
    for (int o = 16; o; o >>= 1) s += __shfl_xor_sync(0xffffffffu, s, o);
    __shared__ float shs[8];
    if ((t & 31) == 0) shs[t >> 5] = s;
    __syncthreads();
    if (t < 32) {
        float s2 = (t < 8) ? shs[t] : 0.f;
        #pragma unroll
        for (int o = 4; o; o >>= 1) s2 += __shfl_xor_sync(0xffffffffu, s2, o);
        if (t == 0) shs[0] = s2;
    }
    __syncthreads();
    const float inv = 1.f / shs[0];

    #pragma unroll
    for (int i = 0; i < 2; i++) {
        float4 o;
        o.x = to_tf32(vals[i*4+0] * inv); o.y = to_tf32(vals[i*4+1] * inv);
        o.z = to_tf32(vals[i*4+2] * inv); o.w = to_tf32(vals[i*4+3] * inv);
        ((float4*)p)[t + i * 256] = o;
    }
}

// ---------------------------------------------------------------------------
// TF32 tensor-core GEMM, cp.async double-buffered.
// Operands are PRE-ROUNDED to tf32 (by producer kernels / weight round pass),
// so raw bytes flow straight through cp.async.
// NT=true:  C[M,N] = A[M,K] * B[N,K]^T   (both K-contiguous)
// NT=false: C[M,N] = A[M,K] * B[K,N]     (B row-major [K,N])
// smem layouts:  As[m][k] stride BK+4 (=36 ≡ 4 mod 32 -> conflict-free frags)
//                Bs NT: [n][k] stride BK+4;  Bs NN: [k][n] stride BN+8.
// ---------------------------------------------------------------------------
template<int BM, int BN, int BK, int WM, int WN,
         bool NT, bool BIAS, bool RELU, bool RESID, bool ROUND>
__global__ __launch_bounds__((BM/WM)*(BN/WN)*32) void mma_gemm_kernel(
    const float* __restrict__ A, const float* __restrict__ Bm,
    const float* __restrict__ bias, const float* __restrict__ resid,
    float* __restrict__ C, int Kdim,
    int lda, int ldb, int ldc,
    long long sAb, long long sAh, long long sBb, long long sBh,
    long long sCb, long long sCh, int Hdiv)
{
    constexpr int WARPS_M = BM / WM;
    constexpr int WARPS_N = BN / WN;
    constexpr int THREADS = WARPS_M * WARPS_N * 32;
    constexpr int MT  = WM / 16;
    constexpr int NTL = WN / 8;
    constexpr int KS  = BK / 8;
    constexpr int AS  = BK + 4;                      // A smem row stride
    constexpr int BSS = NT ? (BK + 4) : (BN + 8);    // B smem row stride
    constexpr int A_TILE = BM * AS;
    constexpr int B_TILE = NT ? (BN * BSS) : (BK * BSS);

    extern __shared__ float smem[];
    float* As_base = smem;
    float* Bs_base = smem + 2 * A_TILE;

    const int z = blockIdx.z;
    const int zb = z / Hdiv;
    const int zh = z - zb * Hdiv;
    A  += (size_t)zb * sAb + (size_t)zh * sAh;
    Bm += (size_t)zb * sBb + (size_t)zh * sBh;
    C  += (size_t)zb * sCb + (size_t)zh * sCh;

    const int tid  = threadIdx.x;
    const int warp = tid >> 5;
    const int lane = tid & 31;
    const int g  = lane >> 2;
    const int tg = lane & 3;
    const int warp_m = warp / WARPS_N;
    const int warp_n = warp % WARPS_N;

    const int block_m = blockIdx.y * BM;
    const int block_n = blockIdx.x * BN;

    const uint32_t sA0 = (uint32_t)__cvta_generic_to_shared(As_base);
    const uint32_t sB0 = (uint32_t)__cvta_generic_to_shared(Bs_base);

    float acc[MT][NTL][4];
    #pragma unroll
    for (int i = 0; i < MT; i++)
        #pragma unroll
        for (int j = 0; j < NTL; j++)
            #pragma unroll
            for (int r = 0; r < 4; r++) acc[i][j][r] = 0.f;

    auto load_tile = [&](int k0, int st) {
        constexpr int A_IT = (BM * BK / 4) / THREADS;
        #pragma unroll
        for (int i = 0; i < A_IT; i++) {
            const int idx = tid + i * THREADS;
            const int r = idx / (BK / 4), c = idx % (BK / 4);
            cp16(sA0 + (uint32_t)(st * A_TILE + r * AS + c * 4) * 4u,
                 &A[(size_t)(block_m + r) * lda + k0 + c * 4]);
        }
        if (NT) {
            constexpr int B_IT = (BN * BK / 4) / THREADS;
            #pragma unroll
            for (int i = 0; i < B_IT; i++) {
                const int idx = tid + i * THREADS;
                const int r = idx / (BK / 4), c = idx % (BK / 4);
                cp16(sB0 + (uint32_t)(st * B_TILE + r * BSS + c * 4) * 4u,
                     &Bm[(size_t)(block_n + r) * ldb + k0 + c * 4]);
            }
        } else {
            constexpr int B_IT = (BK * BN / 4) / THREADS;
            #pragma unroll
            for (int i = 0; i < B_IT; i++) {
                const int idx = tid + i * THREADS;
                const int r = idx / (BN / 4), c = idx % (BN / 4);
                cp16(sB0 + (uint32_t)(st * B_TILE + r * BSS + c * 4) * 4u,
                     &Bm[(size_t)(k0 + r) * ldb + block_n + c * 4]);
            }
        }
    };

    const int KT = Kdim / BK;
    load_tile(0, 0);
    cp_commit();

    for (int kt = 0; kt < KT; kt++) {
        if (kt + 1 < KT) {
            load_tile((kt + 1) * BK, (kt + 1) & 1);
            cp_commit();
            cp_wait<1>();
        } else {
            cp_wait<0>();
        }
        __syncthreads();

        const float* Asr = As_base + (kt & 1) * A_TILE;
        const float* Bsr = Bs_base + (kt & 1) * B_TILE;

        #pragma unroll
        for (int ks = 0; ks < KS; ks++) {
            const int kb = ks * 8;
            uint32_t af[MT][4];
            uint32_t bf[NTL][2];
            #pragma unroll
            for (int mt = 0; mt < MT; mt++) {
                const int mb = warp_m * WM + mt * 16 + g;
                af[mt][0] = __float_as_uint(Asr[(size_t)mb * AS + kb + tg]);
                af[mt][1] = __float_as_uint(Asr[(size_t)(mb + 8) * AS + kb + tg]);
                af[mt][2] = __float_as_uint(Asr[(size_t)mb * AS + kb + tg + 4]);
                af[mt][3] = __float_as_uint(Asr[(size_t)(mb + 8) * AS + kb + tg + 4]);
            }
            #pragma unroll
            for (int nt = 0; nt < NTL; nt++) {
                const int nb = warp_n * WN + nt * 8 + g;
                if (NT) {
                    bf[nt][0] = __float_as_uint(Bsr[(size_t)nb * BSS + kb + tg]);
                    bf[nt][1] = __float_as_uint(Bsr[(size_t)nb * BSS + kb + tg + 4]);
                } else {
                    bf[nt][0] = __float_as_uint(Bsr[(size_t)(kb + tg) * BSS + nb]);
                    bf[nt][1] = __float_as_uint(Bsr[(size_t)(kb + tg + 4) * BSS + nb]);
                }
            }
            #pragma unroll
            for (int mt = 0; mt < MT; mt++)
                #pragma unroll
                for (int nt = 0; nt < NTL; nt++)
                    mma_tf32(acc[mt][nt], af[mt], bf[nt]);
        }
        __syncthreads();
    }

    // --- epilogue: float2 stores, optional bias / relu / residual / round ---
    #pragma unroll
    for (int mt = 0; mt < MT; mt++) {
        const int row0 = block_m + warp_m * WM + mt * 16 + g;
        #pragma unroll
        for (int nt = 0; nt < NTL; nt++) {
            const int col = block_n + warp_n * WN + nt * 8 + 2 * tg;
            float2 lo = make_float2(acc[mt][nt][0], acc[mt][nt][1]);
            float2 hi = make_float2(acc[mt][nt][2], acc[mt][nt][3]);
            if (BIAS) {
                const float2 bb = *(const float2*)&bias[col];
                lo.x += bb.x; lo.y += bb.y; hi.x += bb.x; hi.y += bb.y;
            }
            if (RELU) {
                lo.x = fmaxf(lo.x, 0.f); lo.y = fmaxf(lo.y, 0.f);
                hi.x = fmaxf(hi.x, 0.f); hi.y = fmaxf(hi.y, 0.f);
            }
            if (RESID) {
                const float2 r0 = *(const float2*)&resid[(size_t)row0 * ldc + col];
                const float2 r1 = *(const float2*)&resid[(size_t)(row0 + 8) * ldc + col];
                lo.x += r0.x; lo.y += r0.y; hi.x += r1.x; hi.y += r1.y;
            }
            if (ROUND) {
                lo.x = to_tf32(lo.x); lo.y = to_tf32(lo.y);
                hi.x = to_tf32(hi.x); hi.y = to_tf32(hi.y);
            }
            *(float2*)&C[(size_t)row0 * ldc + col]       = lo;
            *(float2*)&C[(size_t)(row0 + 8) * ldc + col] = hi;
        }
    }
}

// ---------------------------------------------------------------------------
// Host-side launch pipeline (graph-capturable: kernel launches only)
// ---------------------------------------------------------------------------
extern "C" void kernel_launch(void* const* d_in, const int* in_sizes, int n_in,
                              void* d_out, int out_size)
{
    const float* x      = (const float*)d_in[0];
    const int*   mask   = (const int*)  d_in[1];
    const float* wq     = (const float*)d_in[2];
    const float* wk     = (const float*)d_in[3];
    const float* wv     = (const float*)d_in[4];
    const float* wo     = (const float*)d_in[5];
    const float* w1     = (const float*)d_in[6];
    const float* b1     = (const float*)d_in[7];
    const float* w2     = (const float*)d_in[8];
    const float* b2     = (const float*)d_in[9];
    const float* alpha1 = (const float*)d_in[10];
    const float* bias1  = (const float*)d_in[11];
    const float* alpha2 = (const float*)d_in[12];
    const float* bias2  = (const float*)d_in[13];
    float* out = (float*)d_out;

    float *xn, *q, *k, *v, *av, *x1, *xn2, *hb, *sc;
    float *wqr, *wkr, *wvr, *wor, *w1r, *w2r;
    cudaGetSymbolAddress((void**)&xn,  g_xn);
    cudaGetSymbolAddress((void**)&q,   g_q);
    cudaGetSymbolAddress((void**)&k,   g_k);
    cudaGetSymbolAddress((void**)&v,   g_v);
    cudaGetSymbolAddress((void**)&av,  g_av);
    cudaGetSymbolAddress((void**)&x1,  g_x1);
    cudaGetSymbolAddress((void**)&xn2, g_xn2);
    cudaGetSymbolAddress((void**)&hb,  g_h);
    cudaGetSymbolAddress((void**)&sc,  g_sc);
    cudaGetSymbolAddress((void**)&wqr, g_wqr);
    cudaGetSymbolAddress((void**)&wkr, g_wkr);
    cudaGetSymbolAddress((void**)&wvr, g_wvr);
    cudaGetSymbolAddress((void**)&wor, g_wor);
    cudaGetSymbolAddress((void**)&w1r, g_w1r);
    cudaGetSymbolAddress((void**)&w2r, g_w2r);

    const long long SD  = (long long)cS * cD;
    const long long SS  = (long long)cS * cS;
    const long long HSS = (long long)cH * SS;

    // smem sizes (must mirror the kernel's constexpr math)
    constexpr int SMEM_NT  = 2 * (128 * 36 + 128 * 36) * 4;       // 73728
    constexpr int SMEM_NN  = 2 * (128 * 36 + 32 * 72) * 4;        // 55296

    // dynamic smem opt-in (idempotent host calls; not stream ops)
    cudaFuncSetAttribute(mma_gemm_kernel<128,128,32,64,32,true,false,false,false,true>,
                         cudaFuncAttributeMaxDynamicSharedMemorySize, SMEM_NT);
    cudaFuncSetAttribute(mma_gemm_kernel<128,128,32,64,32,true,false,false,false,false>,
                         cudaFuncAttributeMaxDynamicSharedMemorySize, SMEM_NT);
    cudaFuncSetAttribute(mma_gemm_kernel<128,128,32,64,32,true,false,false,true,false>,
                         cudaFuncAttributeMaxDynamicSharedMemorySize, SMEM_NT);
    cudaFuncSetAttribute(mma_gemm_kernel<128,128,32,64,32,true,true,true,false,true>,
                         cudaFuncAttributeMaxDynamicSharedMemorySize, SMEM_NT);
    cudaFuncSetAttribute(mma_gemm_kernel<128,128,32,64,32,true,true,false,true,false>,
                         cudaFuncAttributeMaxDynamicSharedMemorySize, SMEM_NT);
    cudaFuncSetAttribute(mma_gemm_kernel<128,64,32,64,32,false,false,false,false,true>,
                         cudaFuncAttributeMaxDynamicSharedMemorySize, SMEM_NN);

    // 0) round weights to tf32 once per launch
    round_tf32_kernel<<<(cD*cD/4 + 255)/256, 256>>>((const float4*)wq, (float4*)wqr, cD*cD/4);
    round_tf32_kernel<<<(cD*cD/4 + 255)/256, 256>>>((const float4*)wk, (float4*)wkr, cD*cD/4);
    round_tf32_kernel<<<(cD*cD/4 + 255)/256, 256>>>((const float4*)wv, (float4*)wvr, cD*cD/4);
    round_tf32_kernel<<<(cD*cD/4 + 255)/256, 256>>>((const float4*)wo, (float4*)wor, cD*cD/4);
    round_tf32_kernel<<<(cDFF*cD/4 + 255)/256, 256>>>((const float4*)w1, (float4*)w1r, cDFF*cD/4);
    round_tf32_kernel<<<(cD*cDFF/4 + 255)/256, 256>>>((const float4*)w2, (float4*)w2r, cD*cDFF/4);

    // 1) LN1 (tf32-rounded output)
    ln_kernel<<<cROWS, 256>>>(x, alpha1, bias1, xn);

    // 2-4) Q/K/V projections (ROUND outputs)
    {
        dim3 grid(cD / 128, cROWS / 128, 1);
        mma_gemm_kernel<128,128,32,64,32,true,false,false,false,true><<<grid, 256, SMEM_NT>>>(
            xn, wqr, nullptr, nullptr, q, cD, cD, cD, cD, 0,0,0,0,0,0, 1);
        mma_gemm_kernel<128,128,32,64,32,true,false,false,false,true><<<grid, 256, SMEM_NT>>>(
            xn, wkr, nullptr, nullptr, k, cD, cD, cD, cD, 0,0,0,0,0,0, 1);
        mma_gemm_kernel<128,128,32,64,32,true,false,false,false,true><<<grid, 256, SMEM_NT>>>(
            xn, wvr, nullptr, nullptr, v, cD, cD, cD, cD, 0,0,0,0,0,0, 1);
    }

    // 5) Scores: per (b,h): S[2048,2048] = Qh * Kh^T
    {
        dim3 grid(cS / 128, cS / 128, cB * cH);
        mma_gemm_kernel<128,128,32,64,32,true,false,false,false,false><<<grid, 256, SMEM_NT>>>(
            q, k, nullptr, nullptr, sc, cDK, cD, cD, cS,
            SD, cDK, SD, cDK, HSS, SS, cH);
    }

    // 6) mask + scale + softmax (in place, rounded output)
    softmax_kernel<<<cB * cH * cS, 256>>>(sc, mask);

    // 7) AV: per (b,h): av[2048,64] = P * Vh  (NN, ROUND output)
    {
        dim3 grid(1, cS / 128, cB * cH);
        mma_gemm_kernel<128,64,32,64,32,false,false,false,false,true><<<grid, 128, SMEM_NN>>>(
            sc, v, nullptr, nullptr, av, cS, cS, cD, cD,
            HSS, SS, SD, cDK, SD, cDK, cH);
    }

    // 8) WO projection + residual: x1 = x + av @ wo^T  (full fp32 out)
    {
        dim3 grid(cD / 128, cROWS / 128, 1);
        mma_gemm_kernel<128,128,32,64,32,true,false,false,true,false><<<grid, 256, SMEM_NT>>>(
            av, wor, nullptr, x, x1, cD, cD, cD, cD, 0,0,0,0,0,0, 1);
    }

    // 9) LN2 (rounded output)
    ln_kernel<<<cROWS, 256>>>(x1, alpha2, bias2, xn2);

    // 10) FFN1: h = relu(xn2 @ w1^T + b1)  (ROUND output)
    {
        dim3 grid(cDFF / 128, cROWS / 128, 1);
        mma_gemm_kernel<128,128,32,64,32,true,true,true,false,true><<<grid, 256, SMEM_NT>>>(
            xn2, w1r, b1, nullptr, hb, cD, cD, cD, cDFF, 0,0,0,0,0,0, 1);
    }

    // 11) FFN2: out = x1 + h @ w2^T + b2  (full fp32 out)
    {
        dim3 grid(cD / 128, cROWS / 128, 1);
        mma_gemm_kernel<128,128,32,64,32,true,true,false,true,false><<<grid, 256, SMEM_NT>>>(
            hb, w2r, b2, x1, out, cDFF, cDFF, cDFF, cD, 0,0,0,0,0,0, 1);
    }
    (void)in_sizes; (void)n_in; (void)out_size;
}

// round 6
// speedup vs baseline: 3.1410x; 1.2037x over previous
#include <cuda_runtime.h>
#include <math.h>
#include <stdint.h>

// Problem constants
namespace {
constexpr int cB   = 2;
constexpr int cS   = 2048;
constexpr int cD   = 1024;
constexpr int cH   = 16;
constexpr int cDK  = 64;     // cD / cH
constexpr int cDFF = 4096;
constexpr int cROWS = cB * cS;          // 4096 token rows
}

// ---------------------------------------------------------------------------
// Static device scratch (allocation-free rule: __device__ globals)
// ---------------------------------------------------------------------------
__device__ float g_xn [(size_t)cROWS * cD];        // LN1 output (tf32-rounded)
__device__ float g_q  [(size_t)cROWS * cD];
__device__ float g_k  [(size_t)cROWS * cD];
__device__ float g_v  [(size_t)cROWS * cD];
__device__ float g_av [(size_t)cROWS * cD];
__device__ float g_x1 [(size_t)cROWS * cD];        // x + av@wo^T (full fp32)
__device__ float g_xn2[(size_t)cROWS * cD];        // LN2 output (tf32-rounded)
__device__ float g_h  [(size_t)cROWS * cDFF];      // FFN hidden (tf32-rounded)
// tf32-rounded weight copies
__device__ float g_wqr[(size_t)cD * cD];
__device__ float g_wkr[(size_t)cD * cD];
__device__ float g_wvr[(size_t)cD * cD];
__device__ float g_wor[(size_t)cD * cD];
__device__ float g_w1r[(size_t)cDFF * cD];
__device__ float g_w2r[(size_t)cD * cDFF];

// ---------------------------------------------------------------------------
// Helpers
// ---------------------------------------------------------------------------
__device__ __forceinline__ float to_tf32(float x) {
    uint32_t u;
    asm("cvt.rna.tf32.f32 %0, %1;" : "=r"(u) : "f"(x));
    return __uint_as_float(u);
}

__device__ __forceinline__ void mma_tf32(float* c, const uint32_t* a, const uint32_t* b) {
    asm volatile(
        "mma.sync.aligned.m16n8k8.row.col.f32.tf32.tf32.f32 "
        "{%0,%1,%2,%3}, {%4,%5,%6,%7}, {%8,%9}, {%0,%1,%2,%3};\n"
        : "+f"(c[0]), "+f"(c[1]), "+f"(c[2]), "+f"(c[3])
        : "r"(a[0]), "r"(a[1]), "r"(a[2]), "r"(a[3]), "r"(b[0]), "r"(b[1]));
}

__device__ __forceinline__ void cp16(uint32_t s, const void* g) {
    asm volatile("cp.async.cg.shared.global [%0], [%1], 16;\n" :: "r"(s), "l"(g));
}
__device__ __forceinline__ void cp_commit() {
    asm volatile("cp.async.commit_group;\n");
}
template<int N> __device__ __forceinline__ void cp_wait() {
    asm volatile("cp.async.wait_group %0;\n" :: "n"(N));
}

// ---------------------------------------------------------------------------
// Elementwise round-to-tf32 (for weight matrices), float4 vectorized.
// ---------------------------------------------------------------------------
__global__ __launch_bounds__(256) void round_tf32_kernel(
    const float4* __restrict__ in, float4* __restrict__ out, int n4)
{
    const int i = blockIdx.x * blockDim.x + threadIdx.x;
    if (i < n4) {
        float4 v = in[i];
        v.x = to_tf32(v.x); v.y = to_tf32(v.y);
        v.z = to_tf32(v.z); v.w = to_tf32(v.w);
        out[i] = v;
    }
}

// ---------------------------------------------------------------------------
// LayerNorm: one block per row of 1024, 256 threads, float4 per thread.
// Matches reference: alpha * (x - mean) / (std_unbiased + eps) + bias
// Output is tf32-rounded (it is only ever consumed as a GEMM operand).
// ---------------------------------------------------------------------------
__global__ __launch_bounds__(256) void ln_kernel(
    const float* __restrict__ x, const float* __restrict__ alpha,
    const float* __restrict__ beta, float* __restrict__ y)
{
    const int row = blockIdx.x;
    const int t = threadIdx.x;
    const float4 v = ((const float4*)(x + (size_t)row * cD))[t];

    float s  = v.x + v.y + v.z + v.w;
    float ss = v.x * v.x + v.y * v.y + v.z * v.z + v.w * v.w;
    #pragma unroll
    for (int o = 16; o; o >>= 1) {
        s  += __shfl_xor_sync(0xffffffffu, s, o);
        ss += __shfl_xor_sync(0xffffffffu, ss, o);
    }
    __shared__ float sh_s[8], sh_ss[8];
    if ((t & 31) == 0) { sh_s[t >> 5] = s; sh_ss[t >> 5] = ss; }
    __syncthreads();
    if (t < 32) {
        float s2  = (t < 8) ? sh_s[t]  : 0.f;
        float ss2 = (t < 8) ? sh_ss[t] : 0.f;
        #pragma unroll
        for (int o = 4; o; o >>= 1) {
            s2  += __shfl_xor_sync(0xffffffffu, s2, o);
            ss2 += __shfl_xor_sync(0xffffffffu, ss2, o);
        }
        if (t == 0) { sh_s[0] = s2; sh_ss[0] = ss2; }
    }
    __syncthreads();
    s = sh_s[0]; ss = sh_ss[0];

    const float mean = s * (1.f / (float)cD);
    const float var  = (ss - s * mean) * (1.f / (float)(cD - 1)); // ddof=1
    const float inv  = 1.f / (sqrtf(var) + 1e-6f);                // (std + eps)

    const float4 a = ((const float4*)alpha)[t];
    const float4 b = ((const float4*)beta)[t];
    float4 o;
    o.x = to_tf32(a.x * (v.x - mean) * inv + b.x);
    o.y = to_tf32(a.y * (v.y - mean) * inv + b.y);
    o.z = to_tf32(a.z * (v.z - mean) * inv + b.z);
    o.w = to_tf32(a.w * (v.w - mean) * inv + b.w);
    ((float4*)(y + (size_t)row * cD))[t] = o;
}

// ---------------------------------------------------------------------------
// Flash attention: per (b,h), per 128-query tile. Online softmax, no score
// tensor. 8 warps x 16 query rows. K/V streamed in 64-key cp.async
// double-buffered tiles. QK^T and PV on tf32 mma fragments; P converted from
// C-layout to A-layout in registers via quad shuffles.
// Q is pre-scaled by 0.125 at fragment load (exact pow2, commutes).
// ---------------------------------------------------------------------------
__global__ __launch_bounds__(256, 1) void flash_kernel(
    const float* __restrict__ q, const float* __restrict__ k,
    const float* __restrict__ v, const int* __restrict__ mask,
    float* __restrict__ o)
{
    extern __shared__ float fsm[];
    constexpr int KST = 68;   // K smem row stride (68 % 32 == 4 -> conflict-free)
    constexpr int VST = 72;   // V smem row stride (72 % 32 == 8 -> conflict-free)
    constexpr int NIT = cS / 64;  // 32 key tiles

    const int qtile = blockIdx.x;
    const int bh = blockIdx.y;
    const int b = bh >> 4;        // cH == 16
    const int h = bh & 15;

    const float* Qb = q + (size_t)b * cS * cD + (size_t)h * cDK;
    const float* Kb = k + (size_t)b * cS * cD + (size_t)h * cDK;
    const float* Vb = v + (size_t)b * cS * cD + (size_t)h * cDK;
    const int*   Mb = mask + (size_t)b * cS;
    float*       Ob = o + (size_t)b * cS * cD + (size_t)h * cDK;

    const int tid = threadIdx.x;
    const int warp = tid >> 5, lane = tid & 31;
    const int g = lane >> 2, tg = lane & 3;

    float* Ks0 = fsm;                              // 2 stages x 64 x KST
    float* Vs0 = fsm + 2 * 64 * KST;               // 2 stages x 64 x VST
    int*   Ms0 = (int*)(fsm + 2 * 64 * KST + 2 * 64 * VST);  // 2 stages x 64

    const uint32_t sKa = (uint32_t)__cvta_generic_to_shared(Ks0);
    const uint32_t sVa = (uint32_t)__cvta_generic_to_shared(Vs0);
    const uint32_t sMa = (uint32_t)__cvta_generic_to_shared(Ms0);

    auto load_kv = [&](int key0, int st) {
        #pragma unroll
        for (int i = 0; i < 4; i++) {
            const int idx = tid + i * 256;
            const int r = idx >> 4, c = idx & 15;        // 64 rows x 16 float4
            cp16(sKa + (uint32_t)(st * 64 * KST + r * KST + c * 4) * 4u,
                 &Kb[(size_t)(key0 + r) * cD + c * 4]);
            cp16(sVa + (uint32_t)(st * 64 * VST + r * VST + c * 4) * 4u,
                 &Vb[(size_t)(key0 + r) * cD + c * 4]);
        }
        if (tid < 16)
            cp16(sMa + (uint32_t)(st * 64 + tid * 4) * 4u, &Mb[key0 + tid * 4]);
    };

    // Q fragments for this warp's 16 rows (scaled by 1/sqrt(DK) = 0.125)
    const int qr = qtile * 128 + warp * 16;
    uint32_t qf[8][4];
    #pragma unroll
    for (int kt = 0; kt < 8; kt++) {
        qf[kt][0] = __float_as_uint(Qb[(size_t)(qr + g)     * cD + kt * 8 + tg    ] * 0.125f);
        qf[kt][1] = __float_as_uint(Qb[(size_t)(qr + g + 8) * cD + kt * 8 + tg    ] * 0.125f);
        qf[kt][2] = __float_as_uint(Qb[(size_t)(qr + g)     * cD + kt * 8 + tg + 4] * 0.125f);
        qf[kt][3] = __float_as_uint(Qb[(size_t)(qr + g + 8) * cD + kt * 8 + tg + 4] * 0.125f);
    }

    float oacc[8][4];
    #pragma unroll
    for (int i = 0; i < 8; i++)
        #pragma unroll
        for (int r = 0; r < 4; r++) oacc[i][r] = 0.f;
    float m0 = -1e30f, m1 = -1e30f, l0 = 0.f, l1 = 0.f;

    load_kv(0, 0);
    cp_commit();

    for (int it = 0; it < NIT; it++) {
        if (it + 1 < NIT) {
            load_kv((it + 1) * 64, (it + 1) & 1);
            cp_commit();
            cp_wait<1>();
        } else {
            cp_wait<0>();
        }
        __syncthreads();

        const float* Ks = Ks0 + (it & 1) * 64 * KST;
        const float* Vs = Vs0 + (it & 1) * 64 * VST;
        const int*   Ms = Ms0 + (it & 1) * 64;

        // --- S tile = (Q*0.125) @ K^T : 8 k-steps x 8 n-tiles ---
        float sacc[8][4];
        #pragma unroll
        for (int i = 0; i < 8; i++)
            #pragma unroll
            for (int r = 0; r < 4; r++) sacc[i][r] = 0.f;
        #pragma unroll
        for (int kt = 0; kt < 8; kt++) {
            #pragma unroll
            for (int nt = 0; nt < 8; nt++) {
                uint32_t bf[2];
                bf[0] = __float_as_uint(Ks[(size_t)(nt * 8 + g) * KST + kt * 8 + tg]);
                bf[1] = __float_as_uint(Ks[(size_t)(nt * 8 + g) * KST + kt * 8 + tg + 4]);
                mma_tf32(sacc[nt], qf[kt], bf);
            }
        }

        // --- mask + tile max ---
        float tm0 = -1e30f, tm1 = -1e30f;
        #pragma unroll
        for (int nt = 0; nt < 8; nt++) {
            const int c0 = nt * 8 + 2 * tg;
            const bool ma = Ms[c0] != 0;
            const bool mb = Ms[c0 + 1] != 0;
            if (!ma) { sacc[nt][0] = -1e9f; sacc[nt][2] = -1e9f; }
            if (!mb) { sacc[nt][1] = -1e9f; sacc[nt][3] = -1e9f; }
            tm0 = fmaxf(tm0, fmaxf(sacc[nt][0], sacc[nt][1]));
            tm1 = fmaxf(tm1, fmaxf(sacc[nt][2], sacc[nt][3]));
        }
        tm0 = fmaxf(tm0, __shfl_xor_sync(0xffffffffu, tm0, 1));
        tm0 = fmaxf(tm0, __shfl_xor_sync(0xffffffffu, tm0, 2));
        tm1 = fmaxf(tm1, __shfl_xor_sync(0xffffffffu, tm1, 1));
        tm1 = fmaxf(tm1, __shfl_xor_sync(0xffffffffu, tm1, 2));

        const float mn0 = fmaxf(m0, tm0), mn1 = fmaxf(m1, tm1);
        const float al0 = __expf(m0 - mn0), al1 = __expf(m1 - mn1);
        m0 = mn0; m1 = mn1;

        float rs0 = 0.f, rs1 = 0.f;
        #pragma unroll
        for (int nt = 0; nt < 8; nt++) {
            sacc[nt][0] = __expf(sacc[nt][0] - mn0);
            sacc[nt][1] = __expf(sacc[nt][1] - mn0);
            sacc[nt][2] = __expf(sacc[nt][2] - mn1);
            sacc[nt][3] = __expf(sacc[nt][3] - mn1);
            rs0 += sacc[nt][0] + sacc[nt][1];
            rs1 += sacc[nt][2] + sacc[nt][3];
        }
        rs0 += __shfl_xor_sync(0xffffffffu, rs0, 1);
        rs0 += __shfl_xor_sync(0xffffffffu, rs0, 2);
        rs1 += __shfl_xor_sync(0xffffffffu, rs1, 1);
        rs1 += __shfl_xor_sync(0xffffffffu, rs1, 2);
        l0 = l0 * al0 + rs0;
        l1 = l1 * al1 + rs1;

        #pragma unroll
        for (int nt = 0; nt < 8; nt++) {
            oacc[nt][0] *= al0; oacc[nt][1] *= al0;
            oacc[nt][2] *= al1; oacc[nt][3] *= al1;
        }

        // --- O += P @ V : convert P C-layout -> A-layout via quad shuffles ---
        const int qbase = lane & ~3;
        #pragma unroll
        for (int kt = 0; kt < 8; kt++) {
            const int s0l = qbase + (tg >> 1);
            const int s1l = s0l + 2;
            const float v0 = __shfl_sync(0xffffffffu, sacc[kt][0], s0l);
            const float v1 = __shfl_sync(0xffffffffu, sacc[kt][1], s0l);
            const float v2 = __shfl_sync(0xffffffffu, sacc[kt][2], s0l);
            const float v3 = __shfl_sync(0xffffffffu, sacc[kt][3], s0l);
            const float w0 = __shfl_sync(0xffffffffu, sacc[kt][0], s1l);
            const float w1 = __shfl_sync(0xffffffffu, sacc[kt][1], s1l);
            const float w2 = __shfl_sync(0xffffffffu, sacc[kt][2], s1l);
            const float w3 = __shfl_sync(0xffffffffu, sacc[kt][3], s1l);
            const bool odd = (tg & 1) != 0;
            uint32_t ap[4];
            ap[0] = __float_as_uint(odd ? v1 : v0);  // P[g   ][kt*8+tg  ]
            ap[1] = __float_as_uint(odd ? v3 : v2);  // P[g+8 ][kt*8+tg  ]
            ap[2] = __float_as_uint(odd ? w1 : w0);  // P[g   ][kt*8+tg+4]
            ap[3] = __float_as_uint(odd ? w3 : w2);  // P[g+8 ][kt*8+tg+4]
            #pragma unroll
            for (int nt = 0; nt < 8; nt++) {
                uint32_t bf[2];
                bf[0] = __float_as_uint(Vs[(size_t)(kt * 8 + tg)     * VST + nt * 8 + g]);
                bf[1] = __float_as_uint(Vs[(size_t)(kt * 8 + tg + 4) * VST + nt * 8 + g]);
                mma_tf32(oacc[nt], ap, bf);
            }
        }
        __syncthreads();
    }

    // --- epilogue: O /= l, tf32-round, float2 stores ---
    const float i0 = 1.f / l0, i1 = 1.f / l1;
    #pragma unroll
    for (int nt = 0; nt < 8; nt++) {
        float2 lo = make_float2(to_tf32(oacc[nt][0] * i0), to_tf32(oacc[nt][1] * i0));
        float2 hi = make_float2(to_tf32(oacc[nt][2] * i1), to_tf32(oacc[nt][3] * i1));
        *(float2*)&Ob[(size_t)(qr + g)     * cD + nt * 8 + 2 * tg] = lo;
        *(float2*)&Ob[(size_t)(qr + g + 8) * cD + nt * 8 + 2 * tg] = hi;
    }
}

// ---------------------------------------------------------------------------
// TF32 tensor-core GEMM, cp.async double-buffered (unchanged from R5).
// ---------------------------------------------------------------------------
template<int BM, int BN, int BK, int WM, int WN,
         bool NT, bool BIAS, bool RELU, bool RESID, bool ROUND>
__global__ __launch_bounds__((BM/WM)*(BN/WN)*32) void mma_gemm_kernel(
    const float* __restrict__ A, const float* __restrict__ Bm,
    const float* __restrict__ bias, const float* __restrict__ resid,
    float* __restrict__ C, int Kdim,
    int lda, int ldb, int ldc,
    long long sAb, long long sAh, long long sBb, long long sBh,
    long long sCb, long long sCh, int Hdiv)
{
    constexpr int WARPS_M = BM / WM;
    constexpr int WARPS_N = BN / WN;
    constexpr int THREADS = WARPS_M * WARPS_N * 32;
    constexpr int MT  = WM / 16;
    constexpr int NTL = WN / 8;
    constexpr int KS  = BK / 8;
    constexpr int AS  = BK + 4;
    constexpr int BSS = NT ? (BK + 4) : (BN + 8);
    constexpr int A_TILE = BM * AS;
    constexpr int B_TILE = NT ? (BN * BSS) : (BK * BSS);

    extern __shared__ float smem[];
    float* As_base = smem;
    float* Bs_base = smem + 2 * A_TILE;

    const int z = blockIdx.z;
    const int zb = z / Hdiv;
    const int zh = z - zb * Hdiv;
    A  += (size_t)zb * sAb + (size_t)zh * sAh;
    Bm += (size_t)zb * sBb + (size_t)zh * sBh;
    C  += (size_t)zb * sCb + (size_t)zh * sCh;

    const int tid  = threadIdx.x;
    const int warp = tid >> 5;
    const int lane = tid & 31;
    const int g  = lane >> 2;
    const int tg = lane & 3;
    const int warp_m = warp / WARPS_N;
    const int warp_n = warp % WARPS_N;

    const int block_m = blockIdx.y * BM;
    const int block_n = blockIdx.x * BN;

    const uint32_t sA0 = (uint32_t)__cvta_generic_to_shared(As_base);
    const uint32_t sB0 = (uint32_t)__cvta_generic_to_shared(Bs_base);

    float acc[MT][NTL][4];
    #pragma unroll
    for (int i = 0; i < MT; i++)
        #pragma unroll
        for (int j = 0; j < NTL; j++)
            #pragma unroll
            for (int r = 0; r < 4; r++) acc[i][j][r] = 0.f;

    auto load_tile = [&](int k0, int st) {
        constexpr int A_IT = (BM * BK / 4) / THREADS;
        #pragma unroll
        for (int i = 0; i < A_IT; i++) {
            const int idx = tid + i * THREADS;
            const int r = idx / (BK / 4), c = idx % (BK / 4);
            cp16(sA0 + (uint32_t)(st * A_TILE + r * AS + c * 4) * 4u,
                 &A[(size_t)(block_m + r) * lda + k0 + c * 4]);
        }
        if (NT) {
            constexpr int B_IT = (BN * BK / 4) / THREADS;
            #pragma unroll
            for (int i = 0; i < B_IT; i++) {
                const int idx = tid + i * THREADS;
                const int r = idx / (BK / 4), c = idx % (BK / 4);
                cp16(sB0 + (uint32_t)(st * B_TILE + r * BSS + c * 4) * 4u,
                     &Bm[(size_t)(block_n + r) * ldb + k0 + c * 4]);
            }
        } else {
            constexpr int B_IT = (BK * BN / 4) / THREADS;
            #pragma unroll
            for (int i = 0; i < B_IT; i++) {
                const int idx = tid + i * THREADS;
                const int r = idx / (BN / 4), c = idx % (BN / 4);
                cp16(sB0 + (uint32_t)(st * B_TILE + r * BSS + c * 4) * 4u,
                     &Bm[(size_t)(k0 + r) * ldb + block_n + c * 4]);
            }
        }
    };

    const int KT = Kdim / BK;
    load_tile(0, 0);
    cp_commit();

    for (int kt = 0; kt < KT; kt++) {
        if (kt + 1 < KT) {
            load_tile((kt + 1) * BK, (kt + 1) & 1);
            cp_commit();
            cp_wait<1>();
        } else {
            cp_wait<0>();
        }
        __syncthreads();

        const float* Asr = As_base + (kt & 1) * A_TILE;
        const float* Bsr = Bs_base + (kt & 1) * B_TILE;

        #pragma unroll
        for (int ks = 0; ks < KS; ks++) {
            const int kb = ks * 8;
            uint32_t af[MT][4];
            uint32_t bf[NTL][2];
            #pragma unroll
            for (int mt = 0; mt < MT; mt++) {
                const int mb = warp_m * WM + mt * 16 + g;
                af[mt][0] = __float_as_uint(Asr[(size_t)mb * AS + kb + tg]);
                af[mt][1] = __float_as_uint(Asr[(size_t)(mb + 8) * AS + kb + tg]);
                af[mt][2] = __float_as_uint(Asr[(size_t)mb * AS + kb + tg + 4]);
                af[mt][3] = __float_as_uint(Asr[(size_t)(mb + 8) * AS + kb + tg + 4]);
            }
            #pragma unroll
            for (int nt = 0; nt < NTL; nt++) {
                const int nb = warp_n * WN + nt * 8 + g;
                if (NT) {
                    bf[nt][0] = __float_as_uint(Bsr[(size_t)nb * BSS + kb + tg]);
                    bf[nt][1] = __float_as_uint(Bsr[(size_t)nb * BSS + kb + tg + 4]);
                } else {
                    bf[nt][0] = __float_as_uint(Bsr[(size_t)(kb + tg) * BSS + nb]);
                    bf[nt][1] = __float_as_uint(Bsr[(size_t)(kb + tg + 4) * BSS + nb]);
                }
            }
            #pragma unroll
            for (int mt = 0; mt < MT; mt++)
                #pragma unroll
                for (int nt = 0; nt < NTL; nt++)
                    mma_tf32(acc[mt][nt], af[mt], bf[nt]);
        }
        __syncthreads();
    }

    #pragma unroll
    for (int mt = 0; mt < MT; mt++) {
        const int row0 = block_m + warp_m * WM + mt * 16 + g;
        #pragma unroll
        for (int nt = 0; nt < NTL; nt++) {
            const int col = block_n + warp_n * WN + nt * 8 + 2 * tg;
            float2 lo = make_float2(acc[mt][nt][0], acc[mt][nt][1]);
            float2 hi = make_float2(acc[mt][nt][2], acc[mt][nt][3]);
            if (BIAS) {
                const float2 bb = *(const float2*)&bias[col];
                lo.x += bb.x; lo.y += bb.y; hi.x += bb.x; hi.y += bb.y;
            }
            if (RELU) {
                lo.x = fmaxf(lo.x, 0.f); lo.y = fmaxf(lo.y, 0.f);
                hi.x = fmaxf(hi.x, 0.f); hi.y = fmaxf(hi.y, 0.f);
            }
            if (RESID) {
                const float2 r0 = *(const float2*)&resid[(size_t)row0 * ldc + col];
                const float2 r1 = *(const float2*)&resid[(size_t)(row0 + 8) * ldc + col];
                lo.x += r0.x; lo.y += r0.y; hi.x += r1.x; hi.y += r1.y;
            }
            if (ROUND) {
                lo.x = to_tf32(lo.x); lo.y = to_tf32(lo.y);
                hi.x = to_tf32(hi.x); hi.y = to_tf32(hi.y);
            }
            *(float2*)&C[(size_t)row0 * ldc + col]       = lo;
            *(float2*)&C[(size_t)(row0 + 8) * ldc + col] = hi;
        }
    }
}

// ---------------------------------------------------------------------------
// Host-side launch pipeline (graph-capturable: kernel launches only)
// ---------------------------------------------------------------------------
extern "C" void kernel_launch(void* const* d_in, const int* in_sizes, int n_in,
                              void* d_out, int out_size)
{
    const float* x      = (const float*)d_in[0];
    const int*   mask   = (const int*)  d_in[1];
    const float* wq     = (const float*)d_in[2];
    const float* wk     = (const float*)d_in[3];
    const float* wv     = (const float*)d_in[4];
    const float* wo     = (const float*)d_in[5];
    const float* w1     = (const float*)d_in[6];
    const float* b1     = (const float*)d_in[7];
    const float* w2     = (const float*)d_in[8];
    const float* b2     = (const float*)d_in[9];
    const float* alpha1 = (const float*)d_in[10];
    const float* bias1  = (const float*)d_in[11];
    const float* alpha2 = (const float*)d_in[12];
    const float* bias2  = (const float*)d_in[13];
    float* out = (float*)d_out;

    float *xn, *q, *k, *v, *av, *x1, *xn2, *hb;
    float *wqr, *wkr, *wvr, *wor, *w1r, *w2r;
    cudaGetSymbolAddress((void**)&xn,  g_xn);
    cudaGetSymbolAddress((void**)&q,   g_q);
    cudaGetSymbolAddress((void**)&k,   g_k);
    cudaGetSymbolAddress((void**)&v,   g_v);
    cudaGetSymbolAddress((void**)&av,  g_av);
    cudaGetSymbolAddress((void**)&x1,  g_x1);
    cudaGetSymbolAddress((void**)&xn2, g_xn2);
    cudaGetSymbolAddress((void**)&hb,  g_h);
    cudaGetSymbolAddress((void**)&wqr, g_wqr);
    cudaGetSymbolAddress((void**)&wkr, g_wkr);
    cudaGetSymbolAddress((void**)&wvr, g_wvr);
    cudaGetSymbolAddress((void**)&wor, g_wor);
    cudaGetSymbolAddress((void**)&w1r, g_w1r);
    cudaGetSymbolAddress((void**)&w2r, g_w2r);

    // smem sizes (mirror kernel constexpr math)
    constexpr int SMEM_NT    = 2 * (128 * 36 + 128 * 36) * 4;          // 73728
    constexpr int SMEM_FLASH = (2 * 64 * 68 + 2 * 64 * 72 + 2 * 64) * 4; // 72192

    cudaFuncSetAttribute(mma_gemm_kernel<128,128,32,64,32,true,false,false,false,true>,
                         cudaFuncAttributeMaxDynamicSharedMemorySize, SMEM_NT);
    cudaFuncSetAttribute(mma_gemm_kernel<128,128,32,64,32,true,false,false,true,false>,
                         cudaFuncAttributeMaxDynamicSharedMemorySize, SMEM_NT);
    cudaFuncSetAttribute(mma_gemm_kernel<128,128,32,64,32,true,true,true,false,true>,
                         cudaFuncAttributeMaxDynamicSharedMemorySize, SMEM_NT);
    cudaFuncSetAttribute(mma_gemm_kernel<128,128,32,64,32,true,true,false,true,false>,
                         cudaFuncAttributeMaxDynamicSharedMemorySize, SMEM_NT);
    cudaFuncSetAttribute(flash_kernel,
                         cudaFuncAttributeMaxDynamicSharedMemorySize, SMEM_FLASH);

    // 0) round weights to tf32 once per launch
    round_tf32_kernel<<<(cD*cD/4 + 255)/256, 256>>>((const float4*)wq, (float4*)wqr, cD*cD/4);
    round_tf32_kernel<<<(cD*cD/4 + 255)/256, 256>>>((const float4*)wk, (float4*)wkr, cD*cD/4);
    round_tf32_kernel<<<(cD*cD/4 + 255)/256, 256>>>((const float4*)wv, (float4*)wvr, cD*cD/4);
    round_tf32_kernel<<<(cD*cD/4 + 255)/256, 256>>>((const float4*)wo, (float4*)wor, cD*cD/4);
    round_tf32_kernel<<<(cDFF*cD/4 + 255)/256, 256>>>((const float4*)w1, (float4*)w1r, cDFF*cD/4);
    round_tf32_kernel<<<(cD*cDFF/4 + 255)/256, 256>>>((const float4*)w2, (float4*)w2r, cD*cDFF/4);

    // 1) LN1 (tf32-rounded output)
    ln_kernel<<<cROWS, 256>>>(x, alpha1, bias1, xn);

    // 2-4) Q/K/V projections (ROUND outputs)
    {
        dim3 grid(cD / 128, cROWS / 128, 1);
        mma_gemm_kernel<128,128,32,64,32,true,false,false,false,true><<<grid, 256, SMEM_NT>>>(
            xn, wqr, nullptr, nullptr, q, cD, cD, cD, cD, 0,0,0,0,0,0, 1);
        mma_gemm_kernel<128,128,32,64,32,true,false,false,false,true><<<grid, 256, SMEM_NT>>>(
            xn, wkr, nullptr, nullptr, k, cD, cD, cD, cD, 0,0,0,0,0,0, 1);
        mma_gemm_kernel<128,128,32,64,32,true,false,false,false,true><<<grid, 256, SMEM_NT>>>(
            xn, wvr, nullptr, nullptr, v, cD, cD, cD, cD, 0,0,0,0,0,0, 1);
    }

    // 5-7) Fused flash attention -> av (tf32-rounded)
    {
        dim3 fgrid(cS / 128, cB * cH);
        flash_kernel<<<fgrid, 256, SMEM_FLASH>>>(q, k, v, mask, av);
    }

    // 8) WO projection + residual: x1 = x + av @ wo^T  (full fp32 out)
    {
        dim3 grid(cD / 128, cROWS / 128, 1);
        mma_gemm_kernel<128,128,32,64,32,true,false,false,true,false><<<grid, 256, SMEM_NT>>>(
            av, wor, nullptr, x, x1, cD, cD, cD, cD, 0,0,0,0,0,0, 1);
    }

    // 9) LN2 (rounded output)
    ln_kernel<<<cROWS, 256>>>(x1, alpha2, bias2, xn2);

    // 10) FFN1: h = relu(xn2 @ w1^T + b1)  (ROUND output)
    {
        dim3 grid(cDFF / 128, cROWS / 128, 1);
        mma_gemm_kernel<128,128,32,64,32,true,true,true,false,true><<<grid, 256, SMEM_NT>>>(
            xn2, w1r, b1, nullptr, hb, cD, cD, cD, cDFF, 0,0,0,0,0,0, 1);
    }

    // 11) FFN2: out = x1 + h @ w2^T + b2  (full fp32 out)
    {
        dim3 grid(cD / 128, cROWS / 128, 1);
        mma_gemm_kernel<128,128,32,64,32,true,true,false,true,false><<<grid, 256, SMEM_NT>>>(
            hb, w2r, b2, x1, out, cDFF, cDFF, cDFF, cD, 0,0,0,0,0,0, 1);
    }
    (void)in_sizes; (void)n_in; (void)out_size;
}

// round 7
// speedup vs baseline: 4.7769x; 1.5208x over previous
#include <cuda_runtime.h>
#include <cuda_fp16.h>
#include <math.h>
#include <stdint.h>

// Problem constants
namespace {
constexpr int cB   = 2;
constexpr int cS   = 2048;
constexpr int cD   = 1024;
constexpr int cH   = 16;
constexpr int cDK  = 64;     // cD / cH
constexpr int cDFF = 4096;
constexpr int cROWS = cB * cS;          // 4096 token rows
constexpr int c3D  = 3 * cD;
}

// ---------------------------------------------------------------------------
// Static device scratch (allocation-free rule: __device__ globals)
// ---------------------------------------------------------------------------
__device__ __half g_xnh [(size_t)cROWS * cD];      // LN1 output (fp16)
__device__ __half g_xn2h[(size_t)cROWS * cD];      // LN2 output (fp16)
__device__ __half g_avh [(size_t)cROWS * cD];      // flash output (fp16)
__device__ __half g_hh  [(size_t)cROWS * cDFF];    // FFN hidden (fp16)
__device__ float  g_qkv [(size_t)cROWS * c3D];     // fused QKV out (tf32-rounded fp32)
__device__ float  g_x1  [(size_t)cROWS * cD];      // x + av@wo^T (full fp32)
// fp16 weight copies
__device__ __half g_wqkvh[(size_t)c3D * cD];       // [wq; wk; wv] rows
__device__ __half g_worh [(size_t)cD * cD];
__device__ __half g_w1h  [(size_t)cDFF * cD];
__device__ __half g_w2h  [(size_t)cD * cDFF];

// ---------------------------------------------------------------------------
// Helpers
// ---------------------------------------------------------------------------
__device__ __forceinline__ float to_tf32(float x) {
    uint32_t u;
    asm("cvt.rna.tf32.f32 %0, %1;" : "=r"(u) : "f"(x));
    return __uint_as_float(u);
}

__device__ __forceinline__ void mma_tf32(float* c, const uint32_t* a, const uint32_t* b) {
    asm volatile(
        "mma.sync.aligned.m16n8k8.row.col.f32.tf32.tf32.f32 "
        "{%0,%1,%2,%3}, {%4,%5,%6,%7}, {%8,%9}, {%0,%1,%2,%3};\n"
        : "+f"(c[0]), "+f"(c[1]), "+f"(c[2]), "+f"(c[3])
        : "r"(a[0]), "r"(a[1]), "r"(a[2]), "r"(a[3]), "r"(b[0]), "r"(b[1]));
}

__device__ __forceinline__ void mma_f16(float* c, const uint32_t* a, const uint32_t* b) {
    asm volatile(
        "mma.sync.aligned.m16n8k16.row.col.f32.f16.f16.f32 "
        "{%0,%1,%2,%3}, {%4,%5,%6,%7}, {%8,%9}, {%0,%1,%2,%3};\n"
        : "+f"(c[0]), "+f"(c[1]), "+f"(c[2]), "+f"(c[3])
        : "r"(a[0]), "r"(a[1]), "r"(a[2]), "r"(a[3]), "r"(b[0]), "r"(b[1]));
}

__device__ __forceinline__ void cp16(uint32_t s, const void* g) {
    asm volatile("cp.async.cg.shared.global [%0], [%1], 16;\n" :: "r"(s), "l"(g));
}
__device__ __forceinline__ void cp_commit() {
    asm volatile("cp.async.commit_group;\n");
}
template<int N> __device__ __forceinline__ void cp_wait() {
    asm volatile("cp.async.wait_group %0;\n" :: "n"(N));
}

// ---------------------------------------------------------------------------
// Elementwise fp32 -> fp16 (for weight matrices), vectorized.
// ---------------------------------------------------------------------------
__global__ __launch_bounds__(256) void round_half_kernel(
    const float4* __restrict__ in, __half* __restrict__ out, int n4)
{
    const int i = blockIdx.x * blockDim.x + threadIdx.x;
    if (i < n4) {
        const float4 v = in[i];
        half2 h01 = __floats2half2_rn(v.x, v.y);
        half2 h23 = __floats2half2_rn(v.z, v.w);
        half2* o = (half2*)(out + (size_t)i * 4);
        o[0] = h01; o[1] = h23;
    }
}

// ---------------------------------------------------------------------------
// LayerNorm: one block per row of 1024, 256 threads, float4 per thread.
// Matches reference: alpha * (x - mean) / (std_unbiased + eps) + bias
// Output fp16 (only ever consumed as a GEMM operand).
// ---------------------------------------------------------------------------
__global__ __launch_bounds__(256) void ln_kernel(
    const float* __restrict__ x, const float* __restrict__ alpha,
    const float* __restrict__ beta, __half* __restrict__ y)
{
    const int row = blockIdx.x;
    const int t = threadIdx.x;
    const float4 v = ((const float4*)(x + (size_t)row * cD))[t];

    float s  = v.x + v.y + v.z + v.w;
    float ss = v.x * v.x + v.y * v.y + v.z * v.z + v.w * v.w;
    #pragma unroll
    for (int o = 16; o; o >>= 1) {
        s  += __shfl_xor_sync(0xffffffffu, s, o);
        ss += __shfl_xor_sync(0xffffffffu, ss, o);
    }
    __shared__ float sh_s[8], sh_ss[8];
    if ((t & 31) == 0) { sh_s[t >> 5] = s; sh_ss[t >> 5] = ss; }
    __syncthreads();
    if (t < 32) {
        float s2  = (t < 8) ? sh_s[t]  : 0.f;
        float ss2 = (t < 8) ? sh_ss[t] : 0.f;
        #pragma unroll
        for (int o = 4; o; o >>= 1) {
            s2  += __shfl_xor_sync(0xffffffffu, s2, o);
            ss2 += __shfl_xor_sync(0xffffffffu, ss2, o);
        }
        if (t == 0) { sh_s[0] = s2; sh_ss[0] = ss2; }
    }
    __syncthreads();
    s = sh_s[0]; ss = sh_ss[0];

    const float mean = s * (1.f / (float)cD);
    const float var  = (ss - s * mean) * (1.f / (float)(cD - 1)); // ddof=1
    const float inv  = 1.f / (sqrtf(var) + 1e-6f);                // (std + eps)

    const float4 a = ((const float4*)alpha)[t];
    const float4 b = ((const float4*)beta)[t];
    half2* yrow = (half2*)(y + (size_t)row * cD);
    yrow[2 * t]     = __floats2half2_rn(a.x * (v.x - mean) * inv + b.x,
                                        a.y * (v.y - mean) * inv + b.y);
    yrow[2 * t + 1] = __floats2half2_rn(a.z * (v.z - mean) * inv + b.z,
                                        a.w * (v.w - mean) * inv + b.w);
}

// ---------------------------------------------------------------------------
// Flash attention (tf32, unchanged math from R6): per (b,h), per 128-query
// tile; online softmax. Q/K/V read from the fused QKV buffer (row stride 3D,
// column offsets 0/D/2D). Output written as fp16 (feeds WO fp16 GEMM).
// ---------------------------------------------------------------------------
__global__ __launch_bounds__(256, 1) void flash_kernel(
    const float* __restrict__ qkv, const int* __restrict__ mask,
    __half* __restrict__ o)
{
    extern __shared__ float fsm[];
    constexpr int KST = 68;   // 68 % 32 == 4 -> conflict-free
    constexpr int VST = 72;   // 72 % 32 == 8 -> conflict-free
    constexpr int NIT = cS / 64;
    constexpr int LD  = c3D;  // qkv row stride

    const int qtile = blockIdx.x;
    const int bh = blockIdx.y;
    const int b = bh >> 4;
    const int h = bh & 15;

    const float* Qb = qkv + (size_t)b * cS * LD + (size_t)h * cDK;
    const float* Kb = qkv + (size_t)b * cS * LD + cD + (size_t)h * cDK;
    const float* Vb = qkv + (size_t)b * cS * LD + 2 * cD + (size_t)h * cDK;
    const int*   Mb = mask + (size_t)b * cS;
    __half*      Ob = o + (size_t)b * cS * cD + (size_t)h * cDK;

    const int tid = threadIdx.x;
    const int warp = tid >> 5, lane = tid & 31;
    const int g = lane >> 2, tg = lane & 3;

    float* Ks0 = fsm;
    float* Vs0 = fsm + 2 * 64 * KST;
    int*   Ms0 = (int*)(fsm + 2 * 64 * KST + 2 * 64 * VST);

    const uint32_t sKa = (uint32_t)__cvta_generic_to_shared(Ks0);
    const uint32_t sVa = (uint32_t)__cvta_generic_to_shared(Vs0);
    const uint32_t sMa = (uint32_t)__cvta_generic_to_shared(Ms0);

    auto load_kv = [&](int key0, int st) {
        #pragma unroll
        for (int i = 0; i < 4; i++) {
            const int idx = tid + i * 256;
            const int r = idx >> 4, c = idx & 15;
            cp16(sKa + (uint32_t)(st * 64 * KST + r * KST + c * 4) * 4u,
                 &Kb[(size_t)(key0 + r) * LD + c * 4]);
            cp16(sVa + (uint32_t)(st * 64 * VST + r * VST + c * 4) * 4u,
                 &Vb[(size_t)(key0 + r) * LD + c * 4]);
        }
        if (tid < 16)
            cp16(sMa + (uint32_t)(st * 64 + tid * 4) * 4u, &Mb[key0 + tid * 4]);
    };

    const int qr = qtile * 128 + warp * 16;
    uint32_t qf[8][4];
    #pragma unroll
    for (int kt = 0; kt < 8; kt++) {
        qf[kt][0] = __float_as_uint(Qb[(size_t)(qr + g)     * LD + kt * 8 + tg    ] * 0.125f);
        qf[kt][1] = __float_as_uint(Qb[(size_t)(qr + g + 8) * LD + kt * 8 + tg    ] * 0.125f);
        qf[kt][2] = __float_as_uint(Qb[(size_t)(qr + g)     * LD + kt * 8 + tg + 4] * 0.125f);
        qf[kt][3] = __float_as_uint(Qb[(size_t)(qr + g + 8) * LD + kt * 8 + tg + 4] * 0.125f);
    }

    float oacc[8][4];
    #pragma unroll
    for (int i = 0; i < 8; i++)
        #pragma unroll
        for (int r = 0; r < 4; r++) oacc[i][r] = 0.f;
    float m0 = -1e30f, m1 = -1e30f, l0 = 0.f, l1 = 0.f;

    load_kv(0, 0);
    cp_commit();

    for (int it = 0; it < NIT; it++) {
        if (it + 1 < NIT) {
            load_kv((it + 1) * 64, (it + 1) & 1);
            cp_commit();
            cp_wait<1>();
        } else {
            cp_wait<0>();
        }
        __syncthreads();

        const float* Ks = Ks0 + (it & 1) * 64 * KST;
        const float* Vs = Vs0 + (it & 1) * 64 * VST;
        const int*   Ms = Ms0 + (it & 1) * 64;

        float sacc[8][4];
        #pragma unroll
        for (int i = 0; i < 8; i++)
            #pragma unroll
            for (int r = 0; r < 4; r++) sacc[i][r] = 0.f;
        #pragma unroll
        for (int kt = 0; kt < 8; kt++) {
            #pragma unroll
            for (int nt = 0; nt < 8; nt++) {
                uint32_t bf[2];
                bf[0] = __float_as_uint(Ks[(size_t)(nt * 8 + g) * KST + kt * 8 + tg]);
                bf[1] = __float_as_uint(Ks[(size_t)(nt * 8 + g) * KST + kt * 8 + tg + 4]);
                mma_tf32(sacc[nt], qf[kt], bf);
            }
        }

        float tm0 = -1e30f, tm1 = -1e30f;
        #pragma unroll
        for (int nt = 0; nt < 8; nt++) {
            const int c0 = nt * 8 + 2 * tg;
            const bool ma = Ms[c0] != 0;
            const bool mb = Ms[c0 + 1] != 0;
            if (!ma) { sacc[nt][0] = -1e9f; sacc[nt][2] = -1e9f; }
            if (!mb) { sacc[nt][1] = -1e9f; sacc[nt][3] = -1e9f; }
            tm0 = fmaxf(tm0, fmaxf(sacc[nt][0], sacc[nt][1]));
            tm1 = fmaxf(tm1, fmaxf(sacc[nt][2], sacc[nt][3]));
        }
        tm0 = fmaxf(tm0, __shfl_xor_sync(0xffffffffu, tm0, 1));
        tm0 = fmaxf(tm0, __shfl_xor_sync(0xffffffffu, tm0, 2));
        tm1 = fmaxf(tm1, __shfl_xor_sync(0xffffffffu, tm1, 1));
        tm1 = fmaxf(tm1, __shfl_xor_sync(0xffffffffu, tm1, 2));

        const float mn0 = fmaxf(m0, tm0), mn1 = fmaxf(m1, tm1);
        const float al0 = __expf(m0 - mn0), al1 = __expf(m1 - mn1);
        m0 = mn0; m1 = mn1;

        float rs0 = 0.f, rs1 = 0.f;
        #pragma unroll
        for (int nt = 0; nt < 8; nt++) {
            sacc[nt][0] = __expf(sacc[nt][0] - mn0);
            sacc[nt][1] = __expf(sacc[nt][1] - mn0);
            sacc[nt][2] = __expf(sacc[nt][2] - mn1);
            sacc[nt][3] = __expf(sacc[nt][3] - mn1);
            rs0 += sacc[nt][0] + sacc[nt][1];
            rs1 += sacc[nt][2] + sacc[nt][3];
        }
        rs0 += __shfl_xor_sync(0xffffffffu, rs0, 1);
        rs0 += __shfl_xor_sync(0xffffffffu, rs0, 2);
        rs1 += __shfl_xor_sync(0xffffffffu, rs1, 1);
        rs1 += __shfl_xor_sync(0xffffffffu, rs1, 2);
        l0 = l0 * al0 + rs0;
        l1 = l1 * al1 + rs1;

        #pragma unroll
        for (int nt = 0; nt < 8; nt++) {
            oacc[nt][0] *= al0; oacc[nt][1] *= al0;
            oacc[nt][2] *= al1; oacc[nt][3] *= al1;
        }

        const int qbase = lane & ~3;
        #pragma unroll
        for (int kt = 0; kt < 8; kt++) {
            const int s0l = qbase + (tg >> 1);
            const int s1l = s0l + 2;
            const float v0 = __shfl_sync(0xffffffffu, sacc[kt][0], s0l);
            const float v1 = __shfl_sync(0xffffffffu, sacc[kt][1], s0l);
            const float v2 = __shfl_sync(0xffffffffu, sacc[kt][2], s0l);
            const float v3 = __shfl_sync(0xffffffffu, sacc[kt][3], s0l);
            const float w0 = __shfl_sync(0xffffffffu, sacc[kt][0], s1l);
            const float w1 = __shfl_sync(0xffffffffu, sacc[kt][1], s1l);
            const float w2 = __shfl_sync(0xffffffffu, sacc[kt][2], s1l);
            const float w3 = __shfl_sync(0xffffffffu, sacc[kt][3], s1l);
            const bool odd = (tg & 1) != 0;
            uint32_t ap[4];
            ap[0] = __float_as_uint(odd ? v1 : v0);
            ap[1] = __float_as_uint(odd ? v3 : v2);
            ap[2] = __float_as_uint(odd ? w1 : w0);
            ap[3] = __float_as_uint(odd ? w3 : w2);
            #pragma unroll
            for (int nt = 0; nt < 8; nt++) {
                uint32_t bf[2];
                bf[0] = __float_as_uint(Vs[(size_t)(kt * 8 + tg)     * VST + nt * 8 + g]);
                bf[1] = __float_as_uint(Vs[(size_t)(kt * 8 + tg + 4) * VST + nt * 8 + g]);
                mma_tf32(oacc[nt], ap, bf);
            }
        }
        __syncthreads();
    }

    const float i0 = 1.f / l0, i1 = 1.f / l1;
    #pragma unroll
    for (int nt = 0; nt < 8; nt++) {
        *(half2*)&Ob[(size_t)(qr + g)     * cD + nt * 8 + 2 * tg] =
            __floats2half2_rn(oacc[nt][0] * i0, oacc[nt][1] * i0);
        *(half2*)&Ob[(size_t)(qr + g + 8) * cD + nt * 8 + 2 * tg] =
            __floats2half2_rn(oacc[nt][2] * i1, oacc[nt][3] * i1);
    }
}

// ---------------------------------------------------------------------------
// FP16 tensor-core GEMM (mma.sync m16n8k16), cp.async double-buffered.
// C[M,N] = A[M,K] * B[N,K]^T, A/B fp16 K-contiguous, fp32 accumulate.
// smem: half tiles, row stride BK+8 = 72 halves (144 B -> word stride 36,
// 36 mod 32 == 4 -> conflict-free fragment loads).
// OUTH: C is __half*, else float*.
// ---------------------------------------------------------------------------
template<int BM, int BN, int BK, int WM, int WN,
         bool BIAS, bool RELU, bool RESID, bool ROUND, bool OUTH>
__global__ __launch_bounds__((BM/WM)*(BN/WN)*32) void hgemm_kernel(
    const __half* __restrict__ A, const __half* __restrict__ Bm,
    const float* __restrict__ bias, const float* __restrict__ resid,
    void* __restrict__ Cv, int Kdim, int lda, int ldb, int ldc)
{
    constexpr int WARPS_M = BM / WM;
    constexpr int WARPS_N = BN / WN;
    constexpr int THREADS = WARPS_M * WARPS_N * 32;
    constexpr int MT  = WM / 16;
    constexpr int NTL = WN / 8;
    constexpr int KS  = BK / 16;
    constexpr int AS  = BK + 8;            // half stride
    constexpr int A_TILE = BM * AS;        // halves
    constexpr int B_TILE = BN * AS;

    extern __shared__ __half hsm[];
    __half* As_base = hsm;
    __half* Bs_base = hsm + 2 * A_TILE;

    const int tid  = threadIdx.x;
    const int warp = tid >> 5;
    const int lane = tid & 31;
    const int g  = lane >> 2;
    const int tg = lane & 3;
    const int warp_m = warp / WARPS_N;
    const int warp_n = warp % WARPS_N;

    const int block_m = blockIdx.y * BM;
    const int block_n = blockIdx.x * BN;

    const uint32_t sA0 = (uint32_t)__cvta_generic_to_shared(As_base);
    const uint32_t sB0 = (uint32_t)__cvta_generic_to_shared(Bs_base);

    float acc[MT][NTL][4];
    #pragma unroll
    for (int i = 0; i < MT; i++)
        #pragma unroll
        for (int j = 0; j < NTL; j++)
            #pragma unroll
            for (int r = 0; r < 4; r++) acc[i][j][r] = 0.f;

    auto load_tile = [&](int k0, int st) {
        constexpr int A_IT = (BM * BK / 8) / THREADS;
        #pragma unroll
        for (int i = 0; i < A_IT; i++) {
            const int idx = tid + i * THREADS;
            const int r = idx / (BK / 8), c = idx % (BK / 8);
            cp16(sA0 + (uint32_t)(st * A_TILE + r * AS + c * 8) * 2u,
                 &A[(size_t)(block_m + r) * lda + k0 + c * 8]);
        }
        constexpr int B_IT = (BN * BK / 8) / THREADS;
        #pragma unroll
        for (int i = 0; i < B_IT; i++) {
            const int idx = tid + i * THREADS;
            const int r = idx / (BK / 8), c = idx % (BK / 8);
            cp16(sB0 + (uint32_t)(st * B_TILE + r * AS + c * 8) * 2u,
                 &Bm[(size_t)(block_n + r) * ldb + k0 + c * 8]);
        }
    };

    const int KT = Kdim / BK;
    load_tile(0, 0);
    cp_commit();

    for (int kt = 0; kt < KT; kt++) {
        if (kt + 1 < KT) {
            load_tile((kt + 1) * BK, (kt + 1) & 1);
            cp_commit();
            cp_wait<1>();
        } else {
            cp_wait<0>();
        }
        __syncthreads();

        const __half* Asr = As_base + (kt & 1) * A_TILE;
        const __half* Bsr = Bs_base + (kt & 1) * B_TILE;

        #pragma unroll
        for (int ks = 0; ks < KS; ks++) {
            const int kb = ks * 16;
            uint32_t af[MT][4];
            uint32_t bf[NTL][2];
            #pragma unroll
            for (int mt = 0; mt < MT; mt++) {
                const int mb = warp_m * WM + mt * 16 + g;
                af[mt][0] = *(const uint32_t*)&Asr[(size_t)mb * AS + kb + 2 * tg];
                af[mt][1] = *(const uint32_t*)&Asr[(size_t)(mb + 8) * AS + kb + 2 * tg];
                af[mt][2] = *(const uint32_t*)&Asr[(size_t)mb * AS + kb + 2 * tg + 8];
                af[mt][3] = *(const uint32_t*)&Asr[(size_t)(mb + 8) * AS + kb + 2 * tg + 8];
            }
            #pragma unroll
            for (int nt = 0; nt < NTL; nt++) {
                const int nb = warp_n * WN + nt * 8 + g;
                bf[nt][0] = *(const uint32_t*)&Bsr[(size_t)nb * AS + kb + 2 * tg];
                bf[nt][1] = *(const uint32_t*)&Bsr[(size_t)nb * AS + kb + 2 * tg + 8];
            }
            #pragma unroll
            for (int mt = 0; mt < MT; mt++)
                #pragma unroll
                for (int nt = 0; nt < NTL; nt++)
                    mma_f16(acc[mt][nt], af[mt], bf[nt]);
        }
        __syncthreads();
    }

    // --- epilogue ---
    #pragma unroll
    for (int mt = 0; mt < MT; mt++) {
        const int row0 = block_m + warp_m * WM + mt * 16 + g;
        #pragma unroll
        for (int nt = 0; nt < NTL; nt++) {
            const int col = block_n + warp_n * WN + nt * 8 + 2 * tg;
            float2 lo = make_float2(acc[mt][nt][0], acc[mt][nt][1]);
            float2 hi = make_float2(acc[mt][nt][2], acc[mt][nt][3]);
            if (BIAS) {
                const float2 bb = *(const float2*)&bias[col];
                lo.x += bb.x; lo.y += bb.y; hi.x += bb.x; hi.y += bb.y;
            }
            if (RELU) {
                lo.x = fmaxf(lo.x, 0.f); lo.y = fmaxf(lo.y, 0.f);
                hi.x = fmaxf(hi.x, 0.f); hi.y = fmaxf(hi.y, 0.f);
            }
            if (RESID) {
                const float2 r0 = *(const float2*)&resid[(size_t)row0 * ldc + col];
                const float2 r1 = *(const float2*)&resid[(size_t)(row0 + 8) * ldc + col];
                lo.x += r0.x; lo.y += r0.y; hi.x += r1.x; hi.y += r1.y;
            }
            if (OUTH) {
                __half* C = (__half*)Cv;
                *(half2*)&C[(size_t)row0 * ldc + col]       = __floats2half2_rn(lo.x, lo.y);
                *(half2*)&C[(size_t)(row0 + 8) * ldc + col] = __floats2half2_rn(hi.x, hi.y);
            } else {
                float* C = (float*)Cv;
                if (ROUND) {
                    lo.x = to_tf32(lo.x); lo.y = to_tf32(lo.y);
                    hi.x = to_tf32(hi.x); hi.y = to_tf32(hi.y);
                }
                *(float2*)&C[(size_t)row0 * ldc + col]       = lo;
                *(float2*)&C[(size_t)(row0 + 8) * ldc + col] = hi;
            }
        }
    }
}

// ---------------------------------------------------------------------------
// Host-side launch pipeline (graph-capturable: kernel launches only)
// ---------------------------------------------------------------------------
extern "C" void kernel_launch(void* const* d_in, const int* in_sizes, int n_in,
                              void* d_out, int out_size)
{
    const float* x      = (const float*)d_in[0];
    const int*   mask   = (const int*)  d_in[1];
    const float* wq     = (const float*)d_in[2];
    const float* wk     = (const float*)d_in[3];
    const float* wv     = (const float*)d_in[4];
    const float* wo     = (const float*)d_in[5];
    const float* w1     = (const float*)d_in[6];
    const float* b1     = (const float*)d_in[7];
    const float* w2     = (const float*)d_in[8];
    const float* b2     = (const float*)d_in[9];
    const float* alpha1 = (const float*)d_in[10];
    const float* bias1  = (const float*)d_in[11];
    const float* alpha2 = (const float*)d_in[12];
    const float* bias2  = (const float*)d_in[13];
    float* out = (float*)d_out;

    __half *xnh, *xn2h, *avh, *hh, *wqkvh, *worh, *w1h, *w2h;
    float *qkv, *x1;
    cudaGetSymbolAddress((void**)&xnh,   g_xnh);
    cudaGetSymbolAddress((void**)&xn2h,  g_xn2h);
    cudaGetSymbolAddress((void**)&avh,   g_avh);
    cudaGetSymbolAddress((void**)&hh,    g_hh);
    cudaGetSymbolAddress((void**)&qkv,   g_qkv);
    cudaGetSymbolAddress((void**)&x1,    g_x1);
    cudaGetSymbolAddress((void**)&wqkvh, g_wqkvh);
    cudaGetSymbolAddress((void**)&worh,  g_worh);
    cudaGetSymbolAddress((void**)&w1h,   g_w1h);
    cudaGetSymbolAddress((void**)&w2h,   g_w2h);

    // smem sizes
    constexpr int SMEM_H     = 2 * (128 * 72 + 128 * 72) * 2;            // 73728 B
    constexpr int SMEM_FLASH = (2 * 64 * 68 + 2 * 64 * 72 + 2 * 64) * 4; // 72192 B

    cudaFuncSetAttribute(hgemm_kernel<128,128,64,64,32,false,false,false,true,false>,
                         cudaFuncAttributeMaxDynamicSharedMemorySize, SMEM_H);
    cudaFuncSetAttribute(hgemm_kernel<128,128,64,64,32,false,false,true,false,false>,
                         cudaFuncAttributeMaxDynamicSharedMemorySize, SMEM_H);
    cudaFuncSetAttribute(hgemm_kernel<128,128,64,64,32,true,true,false,false,true>,
                         cudaFuncAttributeMaxDynamicSharedMemorySize, SMEM_H);
    cudaFuncSetAttribute(hgemm_kernel<128,128,64,64,32,true,false,true,false,false>,
                         cudaFuncAttributeMaxDynamicSharedMemorySize, SMEM_H);
    cudaFuncSetAttribute(flash_kernel,
                         cudaFuncAttributeMaxDynamicSharedMemorySize, SMEM_FLASH);

    // 0) weights -> fp16 (wq/wk/wv concatenated)
    round_half_kernel<<<(cD*cD/4 + 255)/256, 256>>>((const float4*)wq, wqkvh, cD*cD/4);
    round_half_kernel<<<(cD*cD/4 + 255)/256, 256>>>((const float4*)wk, wqkvh + (size_t)cD*cD, cD*cD/4);
    round_half_kernel<<<(cD*cD/4 + 255)/256, 256>>>((const float4*)wv, wqkvh + (size_t)2*cD*cD, cD*cD/4);
    round_half_kernel<<<(cD*cD/4 + 255)/256, 256>>>((const float4*)wo, worh, cD*cD/4);
    round_half_kernel<<<(cDFF*cD/4 + 255)/256, 256>>>((const float4*)w1, w1h, cDFF*cD/4);
    round_half_kernel<<<(cD*cDFF/4 + 255)/256, 256>>>((const float4*)w2, w2h, cD*cDFF/4);

    // 1) LN1 -> fp16
    ln_kernel<<<cROWS, 256>>>(x, alpha1, bias1, xnh);

    // 2) Fused QKV projection: [4096,1024] x [3072,1024]^T -> fp32 tf32-rounded
    {
        dim3 grid(c3D / 128, cROWS / 128);
        hgemm_kernel<128,128,64,64,32,false,false,false,true,false><<<grid, 256, SMEM_H>>>(
            xnh, wqkvh, nullptr, nullptr, qkv, cD, cD, cD, c3D);
    }

    // 3) Flash attention -> av (fp16)
    {
        dim3 fgrid(cS / 128, cB * cH);
        flash_kernel<<<fgrid, 256, SMEM_FLASH>>>(qkv, mask, avh);
    }

    // 4) WO projection + residual: x1 = x + av @ wo^T (fp32 out)
    {
        dim3 grid(cD / 128, cROWS / 128);
        hgemm_kernel<128,128,64,64,32,false,false,true,false,false><<<grid, 256, SMEM_H>>>(
            avh, worh, nullptr, x, x1, cD, cD, cD, cD);
    }

    // 5) LN2 -> fp16
    ln_kernel<<<cROWS, 256>>>(x1, alpha2, bias2, xn2h);

    // 6) FFN1: h = relu(xn2 @ w1^T + b1) -> fp16
    {
        dim3 grid(cDFF / 128, cROWS / 128);
        hgemm_kernel<128,128,64,64,32,true,true,false,false,true><<<grid, 256, SMEM_H>>>(
            xn2h, w1h, b1, nullptr, hh, cD, cD, cD, cDFF);
    }

    // 7) FFN2: out = x1 + h @ w2^T + b2 (fp32 out)
    {
        dim3 grid(cD / 128, cROWS / 128);
        hgemm_kernel<128,128,64,64,32,true,false,true,false,false><<<grid, 256, SMEM_H>>>(
            hh, w2h, b2, x1, out, cDFF, cDFF, cDFF, cD);
    }
    (void)in_sizes; (void)n_in; (void)out_size;
}

// round 8
// speedup vs baseline: 5.6881x; 1.1907x over previous
#include <cuda_runtime.h>
#include <cuda_fp16.h>
#include <math.h>
#include <stdint.h>

// Problem constants
namespace {
constexpr int cB   = 2;
constexpr int cS   = 2048;
constexpr int cD   = 1024;
constexpr int cH   = 16;
constexpr int cDK  = 64;     // cD / cH
constexpr int cDFF = 4096;
constexpr int cROWS = cB * cS;          // 4096 token rows
constexpr int c3D  = 3 * cD;
}

// ---------------------------------------------------------------------------
// Static device scratch (allocation-free rule: __device__ globals)
// ---------------------------------------------------------------------------
__device__ __half g_xnh [(size_t)cROWS * cD];      // LN1 output (fp16)
__device__ __half g_xn2h[(size_t)cROWS * cD];      // LN2 output (fp16)
__device__ __half g_avh [(size_t)cROWS * cD];      // flash output (fp16)
__device__ __half g_hh  [(size_t)cROWS * cDFF];    // FFN hidden (fp16)
__device__ __half g_qkvh[(size_t)cROWS * c3D];     // fused QKV out (fp16)
__device__ float  g_x1  [(size_t)cROWS * cD];      // x + av@wo^T (full fp32)
// fp16 weight copies
__device__ __half g_wqkvh[(size_t)c3D * cD];       // [wq; wk; wv] rows
__device__ __half g_worh [(size_t)cD * cD];
__device__ __half g_w1h  [(size_t)cDFF * cD];
__device__ __half g_w2h  [(size_t)cD * cDFF];

// ---------------------------------------------------------------------------
// Helpers
// ---------------------------------------------------------------------------
__device__ __forceinline__ void mma_f16(float* c, const uint32_t* a, const uint32_t* b) {
    asm volatile(
        "mma.sync.aligned.m16n8k16.row.col.f32.f16.f16.f32 "
        "{%0,%1,%2,%3}, {%4,%5,%6,%7}, {%8,%9}, {%0,%1,%2,%3};\n"
        : "+f"(c[0]), "+f"(c[1]), "+f"(c[2]), "+f"(c[3])
        : "r"(a[0]), "r"(a[1]), "r"(a[2]), "r"(a[3]), "r"(b[0]), "r"(b[1]));
}

__device__ __forceinline__ void cp16(uint32_t s, const void* g) {
    asm volatile("cp.async.cg.shared.global [%0], [%1], 16;\n" :: "r"(s), "l"(g));
}
__device__ __forceinline__ void cp_commit() {
    asm volatile("cp.async.commit_group;\n");
}
template<int N> __device__ __forceinline__ void cp_wait() {
    asm volatile("cp.async.wait_group %0;\n" :: "n"(N));
}

__device__ __forceinline__ void ldm_x4_t(uint32_t& d0, uint32_t& d1,
                                         uint32_t& d2, uint32_t& d3, uint32_t addr) {
    asm volatile("ldmatrix.sync.aligned.m8n8.x4.trans.shared.b16 {%0,%1,%2,%3}, [%4];"
                 : "=r"(d0), "=r"(d1), "=r"(d2), "=r"(d3) : "r"(addr));
}

__device__ __forceinline__ uint32_t packh2(float a, float b) {
    __half2 h = __floats2half2_rn(a, b);
    return *(uint32_t*)&h;
}

// ---------------------------------------------------------------------------
// Elementwise fp32 -> fp16 (weights). 4 float4 loads in flight per thread.
// n4 must be divisible by 1024 (true for all weight shapes here).
// ---------------------------------------------------------------------------
__global__ __launch_bounds__(256) void round_half_kernel(
    const float4* __restrict__ in, __half* __restrict__ out, int n4)
{
    const int i = blockIdx.x * 1024 + threadIdx.x;
    float4 v[4];
    #pragma unroll
    for (int j = 0; j < 4; j++) v[j] = in[i + j * 256];
    #pragma unroll
    for (int j = 0; j < 4; j++) {
        half2* o = (half2*)(out + (size_t)(i + j * 256) * 4);
        o[0] = __floats2half2_rn(v[j].x, v[j].y);
        o[1] = __floats2half2_rn(v[j].z, v[j].w);
    }
}

// ---------------------------------------------------------------------------
// LayerNorm: one block per row of 1024, 256 threads, float4 per thread.
// Matches reference: alpha * (x - mean) / (std_unbiased + eps) + bias
// Output fp16 (only ever consumed as a GEMM operand).
// ---------------------------------------------------------------------------
__global__ __launch_bounds__(256) void ln_kernel(
    const float* __restrict__ x, const float* __restrict__ alpha,
    const float* __restrict__ beta, __half* __restrict__ y)
{
    const int row = blockIdx.x;
    const int t = threadIdx.x;
    const float4 v = ((const float4*)(x + (size_t)row * cD))[t];

    float s  = v.x + v.y + v.z + v.w;
    float ss = v.x * v.x + v.y * v.y + v.z * v.z + v.w * v.w;
    #pragma unroll
    for (int o = 16; o; o >>= 1) {
        s  += __shfl_xor_sync(0xffffffffu, s, o);
        ss += __shfl_xor_sync(0xffffffffu, ss, o);
    }
    __shared__ float sh_s[8], sh_ss[8];
    if ((t & 31) == 0) { sh_s[t >> 5] = s; sh_ss[t >> 5] = ss; }
    __syncthreads();
    if (t < 32) {
        float s2  = (t < 8) ? sh_s[t]  : 0.f;
        float ss2 = (t < 8) ? sh_ss[t] : 0.f;
        #pragma unroll
        for (int o = 4; o; o >>= 1) {
            s2  += __shfl_xor_sync(0xffffffffu, s2, o);
            ss2 += __shfl_xor_sync(0xffffffffu, ss2, o);
        }
        if (t == 0) { sh_s[0] = s2; sh_ss[0] = ss2; }
    }
    __syncthreads();
    s = sh_s[0]; ss = sh_ss[0];

    const float mean = s * (1.f / (float)cD);
    const float var  = (ss - s * mean) * (1.f / (float)(cD - 1)); // ddof=1
    const float inv  = 1.f / (sqrtf(var) + 1e-6f);                // (std + eps)

    const float4 a = ((const float4*)alpha)[t];
    const float4 b = ((const float4*)beta)[t];
    half2* yrow = (half2*)(y + (size_t)row * cD);
    yrow[2 * t]     = __floats2half2_rn(a.x * (v.x - mean) * inv + b.x,
                                        a.y * (v.y - mean) * inv + b.y);
    yrow[2 * t + 1] = __floats2half2_rn(a.z * (v.z - mean) * inv + b.z,
                                        a.w * (v.w - mean) * inv + b.w);
}

// ---------------------------------------------------------------------------
// FP16 flash attention: per (b,h), per 128-query tile. Online softmax.
// QK^T and PV on fp16 m16n8k16. The QK^T C-fragment layout IS the fp16
// A-fragment layout (cols 2tg,2tg+1 at rows g/g+8), so P->A conversion is
// just half2 packing — no shuffles. V B-fragments via ldmatrix.x4.trans.
// Q/K/V read from fused fp16 QKV buffer (row stride 3D).
// ---------------------------------------------------------------------------
__global__ __launch_bounds__(256, 1) void flash_kernel(
    const __half* __restrict__ qkv, const int* __restrict__ mask,
    __half* __restrict__ o)
{
    extern __shared__ __half hfs[];
    constexpr int KSTH = 72;      // K smem row stride in halves (word idx 4g+tg -> conflict-free)
    constexpr int VSTH = 72;      // V smem row stride in halves (144 B, 16B-aligned rows)
    constexpr int NIT = cS / 64;  // 32 key tiles
    constexpr int LD  = c3D;      // qkv row stride (halves)

    const int qtile = blockIdx.x;
    const int bh = blockIdx.y;
    const int b = bh >> 4;
    const int h = bh & 15;

    const __half* Qb = qkv + (size_t)b * cS * LD + (size_t)h * cDK;
    const __half* Kb = qkv + (size_t)b * cS * LD + cD + (size_t)h * cDK;
    const __half* Vb = qkv + (size_t)b * cS * LD + 2 * cD + (size_t)h * cDK;
    const int*    Mb = mask + (size_t)b * cS;
    __half*       Ob = o + (size_t)b * cS * cD + (size_t)h * cDK;

    const int tid = threadIdx.x;
    const int warp = tid >> 5, lane = tid & 31;
    const int g = lane >> 2, tg = lane & 3;

    __half* Ks0 = hfs;                         // 2 stages x 64 x KSTH halves
    __half* Vs0 = hfs + 2 * 64 * KSTH;         // 2 stages x 64 x VSTH halves
    int*    Ms0 = (int*)(hfs + 2 * 64 * KSTH + 2 * 64 * VSTH);  // 2 x 64 ints

    const uint32_t sKa = (uint32_t)__cvta_generic_to_shared(Ks0);
    const uint32_t sVa = (uint32_t)__cvta_generic_to_shared(Vs0);
    const uint32_t sMa = (uint32_t)__cvta_generic_to_shared(Ms0);

    auto load_kv = [&](int key0, int st) {
        #pragma unroll
        for (int i = 0; i < 2; i++) {
            const int idx = tid + i * 256;
            const int r = idx >> 3, c = idx & 7;          // 64 rows x 8 chunks of 8 halves
            cp16(sKa + (uint32_t)(st * 64 * KSTH + r * KSTH + c * 8) * 2u,
                 &Kb[(size_t)(key0 + r) * LD + c * 8]);
            cp16(sVa + (uint32_t)(st * 64 * VSTH + r * VSTH + c * 8) * 2u,
                 &Vb[(size_t)(key0 + r) * LD + c * 8]);
        }
        if (tid < 16)
            cp16(sMa + (uint32_t)(st * 64 + tid * 4) * 4u, &Mb[key0 + tid * 4]);
    };

    // Q fragments, scaled by 1/sqrt(DK)=0.125 (exact pow2). 4 k-steps of 16.
    const int qr = qtile * 128 + warp * 16;
    const __half2 qsc = __floats2half2_rn(0.125f, 0.125f);
    uint32_t qf[4][4];
    #pragma unroll
    for (int kt = 0; kt < 4; kt++) {
        __half2 a0 = *(const __half2*)&Qb[(size_t)(qr + g)     * LD + kt * 16 + 2 * tg];
        __half2 a1 = *(const __half2*)&Qb[(size_t)(qr + g + 8) * LD + kt * 16 + 2 * tg];
        __half2 a2 = *(const __half2*)&Qb[(size_t)(qr + g)     * LD + kt * 16 + 2 * tg + 8];
        __half2 a3 = *(const __half2*)&Qb[(size_t)(qr + g + 8) * LD + kt * 16 + 2 * tg + 8];
        a0 = __hmul2(a0, qsc); a1 = __hmul2(a1, qsc);
        a2 = __hmul2(a2, qsc); a3 = __hmul2(a3, qsc);
        qf[kt][0] = *(uint32_t*)&a0; qf[kt][1] = *(uint32_t*)&a1;
        qf[kt][2] = *(uint32_t*)&a2; qf[kt][3] = *(uint32_t*)&a3;
    }

    // per-lane ldmatrix address components for V (x4.trans):
    // lanes 0-7: k rows 0-7 of n-block j0; 8-15: k rows 8-15 of j0;
    // 16-23: rows 0-7 of j1; 24-31: rows 8-15 of j1.
    const int rowsel = lane & 7;
    const int blk    = (lane >> 3) & 1;
    const int nsel   = (lane >> 4) & 1;
    const uint32_t vlane = (uint32_t)((blk * 8 + rowsel) * VSTH + nsel * 8) * 2u;

    float oacc[8][4];
    #pragma unroll
    for (int i = 0; i < 8; i++)
        #pragma unroll
        for (int r = 0; r < 4; r++) oacc[i][r] = 0.f;
    float m0 = -1e30f, m1 = -1e30f, l0 = 0.f, l1 = 0.f;

    load_kv(0, 0);
    cp_commit();

    for (int it = 0; it < NIT; it++) {
        if (it + 1 < NIT) {
            load_kv((it + 1) * 64, (it + 1) & 1);
            cp_commit();
            cp_wait<1>();
        } else {
            cp_wait<0>();
        }
        __syncthreads();

        const __half* Ks = Ks0 + (it & 1) * 64 * KSTH;
        const uint32_t sVst = sVa + (uint32_t)((it & 1) * 64 * VSTH) * 2u;
        const int*    Ms = Ms0 + (it & 1) * 64;

        // --- S = (Q*0.125) @ K^T : 4 k-steps x 8 n-tiles ---
        float sacc[8][4];
        #pragma unroll
        for (int i = 0; i < 8; i++)
            #pragma unroll
            for (int r = 0; r < 4; r++) sacc[i][r] = 0.f;
        #pragma unroll
        for (int kt = 0; kt < 4; kt++) {
            #pragma unroll
            for (int nt = 0; nt < 8; nt++) {
                uint32_t bf[2];
                bf[0] = *(const uint32_t*)&Ks[(size_t)(nt * 8 + g) * KSTH + kt * 16 + 2 * tg];
                bf[1] = *(const uint32_t*)&Ks[(size_t)(nt * 8 + g) * KSTH + kt * 16 + 2 * tg + 8];
                mma_f16(sacc[nt], qf[kt], bf);
            }
        }

        // --- mask + tile max ---
        float tm0 = -1e30f, tm1 = -1e30f;
        #pragma unroll
        for (int nt = 0; nt < 8; nt++) {
            const int c0 = nt * 8 + 2 * tg;
            const bool ma = Ms[c0] != 0;
            const bool mb = Ms[c0 + 1] != 0;
            if (!ma) { sacc[nt][0] = -1e9f; sacc[nt][2] = -1e9f; }
            if (!mb) { sacc[nt][1] = -1e9f; sacc[nt][3] = -1e9f; }
            tm0 = fmaxf(tm0, fmaxf(sacc[nt][0], sacc[nt][1]));
            tm1 = fmaxf(tm1, fmaxf(sacc[nt][2], sacc[nt][3]));
        }
        tm0 = fmaxf(tm0, __shfl_xor_sync(0xffffffffu, tm0, 1));
        tm0 = fmaxf(tm0, __shfl_xor_sync(0xffffffffu, tm0, 2));
        tm1 = fmaxf(tm1, __shfl_xor_sync(0xffffffffu, tm1, 1));
        tm1 = fmaxf(tm1, __shfl_xor_sync(0xffffffffu, tm1, 2));

        const float mn0 = fmaxf(m0, tm0), mn1 = fmaxf(m1, tm1);
        const float al0 = __expf(m0 - mn0), al1 = __expf(m1 - mn1);
        m0 = mn0; m1 = mn1;

        float rs0 = 0.f, rs1 = 0.f;
        #pragma unroll
        for (int nt = 0; nt < 8; nt++) {
            sacc[nt][0] = __expf(sacc[nt][0] - mn0);
            sacc[nt][1] = __expf(sacc[nt][1] - mn0);
            sacc[nt][2] = __expf(sacc[nt][2] - mn1);
            sacc[nt][3] = __expf(sacc[nt][3] - mn1);
            rs0 += sacc[nt][0] + sacc[nt][1];
            rs1 += sacc[nt][2] + sacc[nt][3];
        }
        rs0 += __shfl_xor_sync(0xffffffffu, rs0, 1);
        rs0 += __shfl_xor_sync(0xffffffffu, rs0, 2);
        rs1 += __shfl_xor_sync(0xffffffffu, rs1, 1);
        rs1 += __shfl_xor_sync(0xffffffffu, rs1, 2);
        l0 = l0 * al0 + rs0;
        l1 = l1 * al1 + rs1;

        #pragma unroll
        for (int nt = 0; nt < 8; nt++) {
            oacc[nt][0] *= al0; oacc[nt][1] *= al0;
            oacc[nt][2] *= al1; oacc[nt][3] *= al1;
        }

        // --- O += P @ V : P packs directly into fp16 A-fragments ---
        #pragma unroll
        for (int kt = 0; kt < 4; kt++) {
            uint32_t ap[4];
            ap[0] = packh2(sacc[2*kt][0],   sacc[2*kt][1]);     // row g,   keys kt*16+2tg..
            ap[1] = packh2(sacc[2*kt][2],   sacc[2*kt][3]);     // row g+8
            ap[2] = packh2(sacc[2*kt+1][0], sacc[2*kt+1][1]);   // row g,   keys +8
            ap[3] = packh2(sacc[2*kt+1][2], sacc[2*kt+1][3]);   // row g+8
            const uint32_t kbase = sVst + vlane + (uint32_t)(kt * 16 * VSTH) * 2u;
            #pragma unroll
            for (int j = 0; j < 4; j++) {
                uint32_t d0, d1, d2, d3;
                ldm_x4_t(d0, d1, d2, d3, kbase + (uint32_t)(j * 16) * 2u);
                uint32_t b01[2] = {d0, d1};
                uint32_t b23[2] = {d2, d3};
                mma_f16(oacc[2*j],     ap, b01);
                mma_f16(oacc[2*j + 1], ap, b23);
            }
        }
        __syncthreads();
    }

    // --- epilogue: O /= l, fp16 stores ---
    const float i0 = 1.f / l0, i1 = 1.f / l1;
    #pragma unroll
    for (int nt = 0; nt < 8; nt++) {
        *(half2*)&Ob[(size_t)(qr + g)     * cD + nt * 8 + 2 * tg] =
            __floats2half2_rn(oacc[nt][0] * i0, oacc[nt][1] * i0);
        *(half2*)&Ob[(size_t)(qr + g + 8) * cD + nt * 8 + 2 * tg] =
            __floats2half2_rn(oacc[nt][2] * i1, oacc[nt][3] * i1);
    }
}

// ---------------------------------------------------------------------------
// FP16 tensor-core GEMM (mma.sync m16n8k16), cp.async double-buffered.
// C[M,N] = A[M,K] * B[N,K]^T, A/B fp16 K-contiguous, fp32 accumulate.
// smem row stride BK+8 = 72 halves (word stride 36 == 4 mod 32, conflict-free).
// OUTH: C is __half*, else float*.
// ---------------------------------------------------------------------------
template<int BM, int BN, int BK, int WM, int WN,
         bool BIAS, bool RELU, bool RESID, bool OUTH>
__global__ __launch_bounds__((BM/WM)*(BN/WN)*32) void hgemm_kernel(
    const __half* __restrict__ A, const __half* __restrict__ Bm,
    const float* __restrict__ bias, const float* __restrict__ resid,
    void* __restrict__ Cv, int Kdim, int lda, int ldb, int ldc)
{
    constexpr int WARPS_M = BM / WM;
    constexpr int WARPS_N = BN / WN;
    constexpr int THREADS = WARPS_M * WARPS_N * 32;
    constexpr int MT  = WM / 16;
    constexpr int NTL = WN / 8;
    constexpr int KS  = BK / 16;
    constexpr int AS  = BK + 8;            // half stride
    constexpr int A_TILE = BM * AS;        // halves
    constexpr int B_TILE = BN * AS;

    extern __shared__ __half hsm[];
    __half* As_base = hsm;
    __half* Bs_base = hsm + 2 * A_TILE;

    const int tid  = threadIdx.x;
    const int warp = tid >> 5;
    const int lane = tid & 31;
    const int g  = lane >> 2;
    const int tg = lane & 3;
    const int warp_m = warp / WARPS_N;
    const int warp_n = warp % WARPS_N;

    const int block_m = blockIdx.y * BM;
    const int block_n = blockIdx.x * BN;

    const uint32_t sA0 = (uint32_t)__cvta_generic_to_shared(As_base);
    const uint32_t sB0 = (uint32_t)__cvta_generic_to_shared(Bs_base);

    float acc[MT][NTL][4];
    #pragma unroll
    for (int i = 0; i < MT; i++)
        #pragma unroll
        for (int j = 0; j < NTL; j++)
            #pragma unroll
            for (int r = 0; r < 4; r++) acc[i][j][r] = 0.f;

    auto load_tile = [&](int k0, int st) {
        constexpr int A_IT = (BM * BK / 8) / THREADS;
        #pragma unroll
        for (int i = 0; i < A_IT; i++) {
            const int idx = tid + i * THREADS;
            const int r = idx / (BK / 8), c = idx % (BK / 8);
            cp16(sA0 + (uint32_t)(st * A_TILE + r * AS + c * 8) * 2u,
                 &A[(size_t)(block_m + r) * lda + k0 + c * 8]);
        }
        constexpr int B_IT = (BN * BK / 8) / THREADS;
        #pragma unroll
        for (int i = 0; i < B_IT; i++) {
            const int idx = tid + i * THREADS;
            const int r = idx / (BK / 8), c = idx % (BK / 8);
            cp16(sB0 + (uint32_t)(st * B_TILE + r * AS + c * 8) * 2u,
                 &Bm[(size_t)(block_n + r) * ldb + k0 + c * 8]);
        }
    };

    const int KT = Kdim / BK;
    load_tile(0, 0);
    cp_commit();

    for (int kt = 0; kt < KT; kt++) {
        if (kt + 1 < KT) {
            load_tile((kt + 1) * BK, (kt + 1) & 1);
            cp_commit();
            cp_wait<1>();
        } else {
            cp_wait<0>();
        }
        __syncthreads();

        const __half* Asr = As_base + (kt & 1) * A_TILE;
        const __half* Bsr = Bs_base + (kt & 1) * B_TILE;

        #pragma unroll
        for (int ks = 0; ks < KS; ks++) {
            const int kb = ks * 16;
            uint32_t af[MT][4];
            uint32_t bf[NTL][2];
            #pragma unroll
            for (int mt = 0; mt < MT; mt++) {
                const int mb = warp_m * WM + mt * 16 + g;
                af[mt][0] = *(const uint32_t*)&Asr[(size_t)mb * AS + kb + 2 * tg];
                af[mt][1] = *(const uint32_t*)&Asr[(size_t)(mb + 8) * AS + kb + 2 * tg];
                af[mt][2] = *(const uint32_t*)&Asr[(size_t)mb * AS + kb + 2 * tg + 8];
                af[mt][3] = *(const uint32_t*)&Asr[(size_t)(mb + 8) * AS + kb + 2 * tg + 8];
            }
            #pragma unroll
            for (int nt = 0; nt < NTL; nt++) {
                const int nb = warp_n * WN + nt * 8 + g;
                bf[nt][0] = *(const uint32_t*)&Bsr[(size_t)nb * AS + kb + 2 * tg];
                bf[nt][1] = *(const uint32_t*)&Bsr[(size_t)nb * AS + kb + 2 * tg + 8];
            }
            #pragma unroll
            for (int mt = 0; mt < MT; mt++)
                #pragma unroll
                for (int nt = 0; nt < NTL; nt++)
                    mma_f16(acc[mt][nt], af[mt], bf[nt]);
        }
        __syncthreads();
    }

    // --- epilogue ---
    #pragma unroll
    for (int mt = 0; mt < MT; mt++) {
        const int row0 = block_m + warp_m * WM + mt * 16 + g;
        #pragma unroll
        for (int nt = 0; nt < NTL; nt++) {
            const int col = block_n + warp_n * WN + nt * 8 + 2 * tg;
            float2 lo = make_float2(acc[mt][nt][0], acc[mt][nt][1]);
            float2 hi = make_float2(acc[mt][nt][2], acc[mt][nt][3]);
            if (BIAS) {
                const float2 bb = *(const float2*)&bias[col];
                lo.x += bb.x; lo.y += bb.y; hi.x += bb.x; hi.y += bb.y;
            }
            if (RELU) {
                lo.x = fmaxf(lo.x, 0.f); lo.y = fmaxf(lo.y, 0.f);
                hi.x = fmaxf(hi.x, 0.f); hi.y = fmaxf(hi.y, 0.f);
            }
            if (RESID) {
                const float2 r0 = *(const float2*)&resid[(size_t)row0 * ldc + col];
                const float2 r1 = *(const float2*)&resid[(size_t)(row0 + 8) * ldc + col];
                lo.x += r0.x; lo.y += r0.y; hi.x += r1.x; hi.y += r1.y;
            }
            if (OUTH) {
                __half* C = (__half*)Cv;
                *(half2*)&C[(size_t)row0 * ldc + col]       = __floats2half2_rn(lo.x, lo.y);
                *(half2*)&C[(size_t)(row0 + 8) * ldc + col] = __floats2half2_rn(hi.x, hi.y);
            } else {
                float* C = (float*)Cv;
                *(float2*)&C[(size_t)row0 * ldc + col]       = lo;
                *(float2*)&C[(size_t)(row0 + 8) * ldc + col] = hi;
            }
        }
    }
}

// ---------------------------------------------------------------------------
// Host-side launch pipeline (graph-capturable: kernel launches only)
// ---------------------------------------------------------------------------
extern "C" void kernel_launch(void* const* d_in, const int* in_sizes, int n_in,
                              void* d_out, int out_size)
{
    const float* x      = (const float*)d_in[0];
    const int*   mask   = (const int*)  d_in[1];
    const float* wq     = (const float*)d_in[2];
    const float* wk     = (const float*)d_in[3];
    const float* wv     = (const float*)d_in[4];
    const float* wo     = (const float*)d_in[5];
    const float* w1     = (const float*)d_in[6];
    const float* b1     = (const float*)d_in[7];
    const float* w2     = (const float*)d_in[8];
    const float* b2     = (const float*)d_in[9];
    const float* alpha1 = (const float*)d_in[10];
    const float* bias1  = (const float*)d_in[11];
    const float* alpha2 = (const float*)d_in[12];
    const float* bias2  = (const float*)d_in[13];
    float* out = (float*)d_out;

    __half *xnh, *xn2h, *avh, *hh, *qkvh, *wqkvh, *worh, *w1h, *w2h;
    float *x1;
    cudaGetSymbolAddress((void**)&xnh,   g_xnh);
    cudaGetSymbolAddress((void**)&xn2h,  g_xn2h);
    cudaGetSymbolAddress((void**)&avh,   g_avh);
    cudaGetSymbolAddress((void**)&hh,    g_hh);
    cudaGetSymbolAddress((void**)&qkvh,  g_qkvh);
    cudaGetSymbolAddress((void**)&x1,    g_x1);
    cudaGetSymbolAddress((void**)&wqkvh, g_wqkvh);
    cudaGetSymbolAddress((void**)&worh,  g_worh);
    cudaGetSymbolAddress((void**)&w1h,   g_w1h);
    cudaGetSymbolAddress((void**)&w2h,   g_w2h);

    // smem sizes
    constexpr int SMEM_H     = 2 * (128 * 72 + 128 * 72) * 2;              // 73728 B
    constexpr int SMEM_FLASH = (2 * 64 * 72 * 2) * 2 + 2 * 64 * 4;         // 37376 B

    cudaFuncSetAttribute(hgemm_kernel<128,128,64,64,32,false,false,false,true>,
                         cudaFuncAttributeMaxDynamicSharedMemorySize, SMEM_H);
    cudaFuncSetAttribute(hgemm_kernel<128,128,64,64,32,false,false,true,false>,
                         cudaFuncAttributeMaxDynamicSharedMemorySize, SMEM_H);
    cudaFuncSetAttribute(hgemm_kernel<128,128,64,64,32,true,true,false,true>,
                         cudaFuncAttributeMaxDynamicSharedMemorySize, SMEM_H);
    cudaFuncSetAttribute(hgemm_kernel<128,128,64,64,32,true,false,true,false>,
                         cudaFuncAttributeMaxDynamicSharedMemorySize, SMEM_H);
    cudaFuncSetAttribute(flash_kernel,
                         cudaFuncAttributeMaxDynamicSharedMemorySize, SMEM_FLASH);

    // 0) weights -> fp16 (wq/wk/wv concatenated)
    round_half_kernel<<<(cD*cD/4)/1024, 256>>>((const float4*)wq, wqkvh, cD*cD/4);
    round_half_kernel<<<(cD*cD/4)/1024, 256>>>((const float4*)wk, wqkvh + (size_t)cD*cD, cD*cD/4);
    round_half_kernel<<<(cD*cD/4)/1024, 256>>>((const float4*)wv, wqkvh + (size_t)2*cD*cD, cD*cD/4);
    round_half_kernel<<<(cD*cD/4)/1024, 256>>>((const float4*)wo, worh, cD*cD/4);
    round_half_kernel<<<(cDFF*cD/4)/1024, 256>>>((const float4*)w1, w1h, cDFF*cD/4);
    round_half_kernel<<<(cD*cDFF/4)/1024, 256>>>((const float4*)w2, w2h, cD*cDFF/4);

    // 1) LN1 -> fp16
    ln_kernel<<<cROWS, 256>>>(x, alpha1, bias1, xnh);

    // 2) Fused QKV projection: [4096,1024] x [3072,1024]^T -> fp16
    {
        dim3 grid(c3D / 128, cROWS / 128);
        hgemm_kernel<128,128,64,64,32,false,false,false,true><<<grid, 256, SMEM_H>>>(
            xnh, wqkvh, nullptr, nullptr, qkvh, cD, cD, cD, c3D);
    }

    // 3) Flash attention -> av (fp16)
    {
        dim3 fgrid(cS / 128, cB * cH);
        flash_kernel<<<fgrid, 256, SMEM_FLASH>>>(qkvh, mask, avh);
    }

    // 4) WO projection + residual: x1 = x + av @ wo^T (fp32 out)
    {
        dim3 grid(cD / 128, cROWS / 128);
        hgemm_kernel<128,128,64,64,32,false,false,true,false><<<grid, 256, SMEM_H>>>(
            avh, worh, nullptr, x, x1, cD, cD, cD, cD);
    }

    // 5) LN2 -> fp16
    ln_kernel<<<cROWS, 256>>>(x1, alpha2, bias2, xn2h);

    // 6) FFN1: h = relu(xn2 @ w1^T + b1) -> fp16
    {
        dim3 grid(cDFF / 128, cROWS / 128);
        hgemm_kernel<128,128,64,64,32,true,true,false,true><<<grid, 256, SMEM_H>>>(
            xn2h, w1h, b1, nullptr, hh, cD, cD, cD, cDFF);
    }

    // 7) FFN2: out = x1 + h @ w2^T + b2 (fp32 out)
    {
        dim3 grid(cD / 128, cROWS / 128);
        hgemm_kernel<128,128,64,64,32,true,false,true,false><<<grid, 256, SMEM_H>>>(
            hh, w2h, b2, x1, out, cDFF, cDFF, cDFF, cD);
    }
    (void)in_sizes; (void)n_in; (void)out_size;
}

// round 11
// speedup vs baseline: 6.8656x; 1.2070x over previous
#include <cuda_runtime.h>
#include <cuda_fp16.h>
#include <math.h>
#include <stdint.h>

// Problem constants
namespace {
constexpr int cB   = 2;
constexpr int cS   = 2048;
constexpr int cD   = 1024;
constexpr int cH   = 16;
constexpr int cDK  = 64;     // cD / cH
constexpr int cDFF = 4096;
constexpr int cROWS = cB * cS;          // 4096 token rows
constexpr int c3D  = 3 * cD;
}

// ---------------------------------------------------------------------------
// Static device scratch (allocation-free rule: __device__ globals)
// ---------------------------------------------------------------------------
__device__ __half g_xnh [(size_t)cROWS * cD];      // LN1 output (fp16)
__device__ __half g_xn2h[(size_t)cROWS * cD];      // LN2 output (fp16)
__device__ __half g_avh [(size_t)cROWS * cD];      // flash output (fp16)
__device__ __half g_hh  [(size_t)cROWS * cDFF];    // FFN hidden (fp16)
__device__ __half g_qkvh[(size_t)cROWS * c3D];     // fused QKV out (fp16)
__device__ float  g_x1  [(size_t)cROWS * cD];      // x + av@wo^T (full fp32)
// fp16 weight copies
__device__ __half g_wqkvh[(size_t)c3D * cD];       // [wq; wk; wv] rows
__device__ __half g_worh [(size_t)cD * cD];
__device__ __half g_w1h  [(size_t)cDFF * cD];
__device__ __half g_w2h  [(size_t)cD * cDFF];

// ---------------------------------------------------------------------------
// Helpers
// ---------------------------------------------------------------------------
__device__ __forceinline__ void mma_f16(float* c, const uint32_t* a, const uint32_t* b) {
    asm volatile(
        "mma.sync.aligned.m16n8k16.row.col.f32.f16.f16.f32 "
        "{%0,%1,%2,%3}, {%4,%5,%6,%7}, {%8,%9}, {%0,%1,%2,%3};\n"
        : "+f"(c[0]), "+f"(c[1]), "+f"(c[2]), "+f"(c[3])
        : "r"(a[0]), "r"(a[1]), "r"(a[2]), "r"(a[3]), "r"(b[0]), "r"(b[1]));
}

__device__ __forceinline__ void cp16(uint32_t s, const void* g) {
    asm volatile("cp.async.cg.shared.global [%0], [%1], 16;\n" :: "r"(s), "l"(g));
}
__device__ __forceinline__ void cp_commit() {
    asm volatile("cp.async.commit_group;\n");
}
template<int N> __device__ __forceinline__ void cp_wait() {
    asm volatile("cp.async.wait_group %0;\n" :: "n"(N));
}

__device__ __forceinline__ void ldm_x4(uint32_t& d0, uint32_t& d1,
                                       uint32_t& d2, uint32_t& d3, uint32_t addr) {
    asm volatile("ldmatrix.sync.aligned.m8n8.x4.shared.b16 {%0,%1,%2,%3}, [%4];"
                 : "=r"(d0), "=r"(d1), "=r"(d2), "=r"(d3) : "r"(addr));
}

__device__ __forceinline__ void ldm_x4_t(uint32_t& d0, uint32_t& d1,
                                         uint32_t& d2, uint32_t& d3, uint32_t addr) {
    asm volatile("ldmatrix.sync.aligned.m8n8.x4.trans.shared.b16 {%0,%1,%2,%3}, [%4];"
                 : "=r"(d0), "=r"(d1), "=r"(d2), "=r"(d3) : "r"(addr));
}

__device__ __forceinline__ uint32_t packh2(float a, float b) {
    __half2 h = __floats2half2_rn(a, b);
    return *(uint32_t*)&h;
}

__device__ __forceinline__ uint32_t smem_u32(const void* p) {
    uint32_t a;
    asm("{ .reg .u64 t; cvta.to.shared.u64 t, %1; cvt.u32.u64 %0, t; }" : "=r"(a) : "l"(p));
    return a;
}

// ---------------------------------------------------------------------------
// Merged weight fp32->fp16 conversion: one launch for all 6 matrices.
// Each block handles 1024 float4 (4096 floats). MLP=4 per thread.
// Segments: wq 256 blocks | wk 256 | wv 256 | wo 256 | w1 1024 | w2 1024.
// ---------------------------------------------------------------------------
__global__ __launch_bounds__(256) void round_all_kernel(
    const float4* __restrict__ wq, const float4* __restrict__ wk,
    const float4* __restrict__ wv, const float4* __restrict__ wo,
    const float4* __restrict__ w1, const float4* __restrict__ w2,
    __half* __restrict__ owqkv, __half* __restrict__ owo,
    __half* __restrict__ ow1, __half* __restrict__ ow2)
{
    const int b = blockIdx.x;
    const float4* in; __half* out; int lb;
    if (b < 256)       { in = wq; out = owqkv;                      lb = b; }
    else if (b < 512)  { in = wk; out = owqkv + (size_t)cD * cD;    lb = b - 256; }
    else if (b < 768)  { in = wv; out = owqkv + (size_t)2 * cD * cD; lb = b - 512; }
    else if (b < 1024) { in = wo; out = owo;                        lb = b - 768; }
    else if (b < 2048) { in = w1; out = ow1;                        lb = b - 1024; }
    else               { in = w2; out = ow2;                        lb = b - 2048; }

    const int i = lb * 1024 + threadIdx.x;
    float4 v[4];
    #pragma unroll
    for (int j = 0; j < 4; j++) v[j] = in[i + j * 256];
    #pragma unroll
    for (int j = 0; j < 4; j++) {
        half2* o = (half2*)(out + (size_t)(i + j * 256) * 4);
        o[0] = __floats2half2_rn(v[j].x, v[j].y);
        o[1] = __floats2half2_rn(v[j].z, v[j].w);
    }
}

// ---------------------------------------------------------------------------
// LayerNorm (exact ddof=1, (std+eps)), fp16 output.
// ---------------------------------------------------------------------------
__global__ __launch_bounds__(256) void ln_kernel(
    const float* __restrict__ x, const float* __restrict__ alpha,
    const float* __restrict__ beta, __half* __restrict__ y)
{
    const int row = blockIdx.x;
    const int t = threadIdx.x;
    const float4 v = ((const float4*)(x + (size_t)row * cD))[t];

    float s  = v.x + v.y + v.z + v.w;
    float ss = v.x * v.x + v.y * v.y + v.z * v.z + v.w * v.w;
    #pragma unroll
    for (int o = 16; o; o >>= 1) {
        s  += __shfl_xor_sync(0xffffffffu, s, o);
        ss += __shfl_xor_sync(0xffffffffu, ss, o);
    }
    __shared__ float sh_s[8], sh_ss[8];
    if ((t & 31) == 0) { sh_s[t >> 5] = s; sh_ss[t >> 5] = ss; }
    __syncthreads();
    if (t < 32) {
        float s2  = (t < 8) ? sh_s[t]  : 0.f;
        float ss2 = (t < 8) ? sh_ss[t] : 0.f;
        #pragma unroll
        for (int o = 4; o; o >>= 1) {
            s2  += __shfl_xor_sync(0xffffffffu, s2, o);
            ss2 += __shfl_xor_sync(0xffffffffu, ss2, o);
        }
        if (t == 0) { sh_s[0] = s2; sh_ss[0] = ss2; }
    }
    __syncthreads();
    s = sh_s[0]; ss = sh_ss[0];

    const float mean = s * (1.f / (float)cD);
    const float var  = (ss - s * mean) * (1.f / (float)(cD - 1));
    const float inv  = 1.f / (sqrtf(var) + 1e-6f);

    const float4 a = ((const float4*)alpha)[t];
    const float4 b = ((const float4*)beta)[t];
    half2* yrow = (half2*)(y + (size_t)row * cD);
    yrow[2 * t]     = __floats2half2_rn(a.x * (v.x - mean) * inv + b.x,
                                        a.y * (v.y - mean) * inv + b.y);
    yrow[2 * t + 1] = __floats2half2_rn(a.z * (v.z - mean) * inv + b.z,
                                        a.w * (v.w - mean) * inv + b.w);
}

// ---------------------------------------------------------------------------
// FP16 flash attention: per (b,h), per 128-query tile. Online softmax.
// K-fragments via ldmatrix.x4 (4 issues/kt instead of 16 LDS);
// V B-fragments via ldmatrix.x4.trans; P packs directly to A-fragments.
// 2 CTAs/SM via launch_bounds.
// ---------------------------------------------------------------------------
__global__ __launch_bounds__(256, 2) void flash_kernel(
    const __half* __restrict__ qkv, const int* __restrict__ mask,
    __half* __restrict__ o)
{
    extern __shared__ __half hfs[];
    constexpr int KSTH = 72;
    constexpr int VSTH = 72;
    constexpr int NIT = cS / 64;
    constexpr int LD  = c3D;

    const int qtile = blockIdx.x;
    const int bh = blockIdx.y;
    const int b = bh >> 4;
    const int h = bh & 15;

    const __half* Qb = qkv + (size_t)b * cS * LD + (size_t)h * cDK;
    const __half* Kb = qkv + (size_t)b * cS * LD + cD + (size_t)h * cDK;
    const __half* Vb = qkv + (size_t)b * cS * LD + 2 * cD + (size_t)h * cDK;
    const int*    Mb = mask + (size_t)b * cS;
    __half*       Ob = o + (size_t)b * cS * cD + (size_t)h * cDK;

    const int tid = threadIdx.x;
    const int warp = tid >> 5, lane = tid & 31;
    const int g = lane >> 2, tg = lane & 3;

    __half* Ks0 = hfs;
    __half* Vs0 = hfs + 2 * 64 * KSTH;
    int*    Ms0 = (int*)(hfs + 2 * 64 * KSTH + 2 * 64 * VSTH);

    const uint32_t sKa = smem_u32(Ks0);
    const uint32_t sVa = smem_u32(Vs0);
    const uint32_t sMa = smem_u32(Ms0);

    auto load_kv = [&](int key0, int st) {
        #pragma unroll
        for (int i = 0; i < 2; i++) {
            const int idx = tid + i * 256;
            const int r = idx >> 3, c = idx & 7;
            cp16(sKa + (uint32_t)(st * 64 * KSTH + r * KSTH + c * 8) * 2u,
                 &Kb[(size_t)(key0 + r) * LD + c * 8]);
            cp16(sVa + (uint32_t)(st * 64 * VSTH + r * VSTH + c * 8) * 2u,
                 &Vb[(size_t)(key0 + r) * LD + c * 8]);
        }
        if (tid < 16)
            cp16(sMa + (uint32_t)(st * 64 + tid * 4) * 4u, &Mb[key0 + tid * 4]);
    };

    const int qr = qtile * 128 + warp * 16;
    const __half2 qsc = __floats2half2_rn(0.125f, 0.125f);
    uint32_t qf[4][4];
    #pragma unroll
    for (int kt = 0; kt < 4; kt++) {
        __half2 a0 = *(const __half2*)&Qb[(size_t)(qr + g)     * LD + kt * 16 + 2 * tg];
        __half2 a1 = *(const __half2*)&Qb[(size_t)(qr + g + 8) * LD + kt * 16 + 2 * tg];
        __half2 a2 = *(const __half2*)&Qb[(size_t)(qr + g)     * LD + kt * 16 + 2 * tg + 8];
        __half2 a3 = *(const __half2*)&Qb[(size_t)(qr + g + 8) * LD + kt * 16 + 2 * tg + 8];
        a0 = __hmul2(a0, qsc); a1 = __hmul2(a1, qsc);
        a2 = __hmul2(a2, qsc); a3 = __hmul2(a3, qsc);
        qf[kt][0] = *(uint32_t*)&a0; qf[kt][1] = *(uint32_t*)&a1;
        qf[kt][2] = *(uint32_t*)&a2; qf[kt][3] = *(uint32_t*)&a3;
    }

    // ldmatrix lane address components
    // K (non-trans, B-operand pairs): row = p*16 + brow, colblock = bcb
    const int brow = (lane & 7) + ((lane >> 4) << 3);
    const int bcb  = (lane >> 3) & 1;
    // V (trans)
    const int rowsel = lane & 7;
    const int blk    = (lane >> 3) & 1;
    const int nsel   = (lane >> 4) & 1;
    const uint32_t vlane = (uint32_t)((blk * 8 + rowsel) * VSTH + nsel * 8) * 2u;
    const uint32_t klane = (uint32_t)(brow * KSTH + bcb * 8) * 2u;

    float oacc[8][4];
    #pragma unroll
    for (int i = 0; i < 8; i++)
        #pragma unroll
        for (int r = 0; r < 4; r++) oacc[i][r] = 0.f;
    float m0 = -1e30f, m1 = -1e30f, l0 = 0.f, l1 = 0.f;

    load_kv(0, 0);
    cp_commit();

    for (int it = 0; it < NIT; it++) {
        if (it + 1 < NIT) {
            load_kv((it + 1) * 64, (it + 1) & 1);
            cp_commit();
            cp_wait<1>();
        } else {
            cp_wait<0>();
        }
        __syncthreads();

        const uint32_t sKst = sKa + (uint32_t)((it & 1) * 64 * KSTH) * 2u;
        const uint32_t sVst = sVa + (uint32_t)((it & 1) * 64 * VSTH) * 2u;
        const int*    Ms = Ms0 + (it & 1) * 64;

        // --- S = (Q*0.125) @ K^T : 4 k-steps x 8 n-tiles (K frags via ldmatrix) ---
        float sacc[8][4];
        #pragma unroll
        for (int i = 0; i < 8; i++)
            #pragma unroll
            for (int r = 0; r < 4; r++) sacc[i][r] = 0.f;
        #pragma unroll
        for (int kt = 0; kt < 4; kt++) {
            #pragma unroll
            for (int p = 0; p < 4; p++) {
                uint32_t d0, d1, d2, d3;
                ldm_x4(d0, d1, d2, d3,
                       sKst + klane + (uint32_t)(p * 16 * KSTH + kt * 16) * 2u);
                uint32_t b0[2] = {d0, d1};
                uint32_t b1[2] = {d2, d3};
                mma_f16(sacc[2*p],     qf[kt], b0);
                mma_f16(sacc[2*p + 1], qf[kt], b1);
            }
        }

        // --- mask + tile max ---
        float tm0 = -1e30f, tm1 = -1e30f;
        #pragma unroll
        for (int nt = 0; nt < 8; nt++) {
            const int c0 = nt * 8 + 2 * tg;
            const bool ma = Ms[c0] != 0;
            const bool mb = Ms[c0 + 1] != 0;
            if (!ma) { sacc[nt][0] = -1e9f; sacc[nt][2] = -1e9f; }
            if (!mb) { sacc[nt][1] = -1e9f; sacc[nt][3] = -1e9f; }
            tm0 = fmaxf(tm0, fmaxf(sacc[nt][0], sacc[nt][1]));
            tm1 = fmaxf(tm1, fmaxf(sacc[nt][2], sacc[nt][3]));
        }
        tm0 = fmaxf(tm0, __shfl_xor_sync(0xffffffffu, tm0, 1));
        tm0 = fmaxf(tm0, __shfl_xor_sync(0xffffffffu, tm0, 2));
        tm1 = fmaxf(tm1, __shfl_xor_sync(0xffffffffu, tm1, 1));
        tm1 = fmaxf(tm1, __shfl_xor_sync(0xffffffffu, tm1, 2));

        const float mn0 = fmaxf(m0, tm0), mn1 = fmaxf(m1, tm1);
        const float al0 = __expf(m0 - mn0), al1 = __expf(m1 - mn1);
        m0 = mn0; m1 = mn1;

        float rs0 = 0.f, rs1 = 0.f;
        #pragma unroll
        for (int nt = 0; nt < 8; nt++) {
            sacc[nt][0] = __expf(sacc[nt][0] - mn0);
            sacc[nt][1] = __expf(sacc[nt][1] - mn0);
            sacc[nt][2] = __expf(sacc[nt][2] - mn1);
            sacc[nt][3] = __expf(sacc[nt][3] - mn1);
            rs0 += sacc[nt][0] + sacc[nt][1];
            rs1 += sacc[nt][2] + sacc[nt][3];
        }
        rs0 += __shfl_xor_sync(0xffffffffu, rs0, 1);
        rs0 += __shfl_xor_sync(0xffffffffu, rs0, 2);
        rs1 += __shfl_xor_sync(0xffffffffu, rs1, 1);
        rs1 += __shfl_xor_sync(0xffffffffu, rs1, 2);
        l0 = l0 * al0 + rs0;
        l1 = l1 * al1 + rs1;

        #pragma unroll
        for (int nt = 0; nt < 8; nt++) {
            oacc[nt][0] *= al0; oacc[nt][1] *= al0;
            oacc[nt][2] *= al1; oacc[nt][3] *= al1;
        }

        // --- O += P @ V : P packs directly into fp16 A-fragments ---
        #pragma unroll
        for (int kt = 0; kt < 4; kt++) {
            uint32_t ap[4];
            ap[0] = packh2(sacc[2*kt][0],   sacc[2*kt][1]);
            ap[1] = packh2(sacc[2*kt][2],   sacc[2*kt][3]);
            ap[2] = packh2(sacc[2*kt+1][0], sacc[2*kt+1][1]);
            ap[3] = packh2(sacc[2*kt+1][2], sacc[2*kt+1][3]);
            const uint32_t kbase = sVst + vlane + (uint32_t)(kt * 16 * VSTH) * 2u;
            #pragma unroll
            for (int j = 0; j < 4; j++) {
                uint32_t d0, d1, d2, d3;
                ldm_x4_t(d0, d1, d2, d3, kbase + (uint32_t)(j * 16) * 2u);
                uint32_t b01[2] = {d0, d1};
                uint32_t b23[2] = {d2, d3};
                mma_f16(oacc[2*j],     ap, b01);
                mma_f16(oacc[2*j + 1], ap, b23);
            }
        }
        __syncthreads();
    }

    const float i0 = 1.f / l0, i1 = 1.f / l1;
    #pragma unroll
    for (int nt = 0; nt < 8; nt++) {
        *(half2*)&Ob[(size_t)(qr + g)     * cD + nt * 8 + 2 * tg] =
            __floats2half2_rn(oacc[nt][0] * i0, oacc[nt][1] * i0);
        *(half2*)&Ob[(size_t)(qr + g + 8) * cD + nt * 8 + 2 * tg] =
            __floats2half2_rn(oacc[nt][2] * i1, oacc[nt][3] * i1);
    }
}

// ---------------------------------------------------------------------------
// FP16 tensor-core GEMM (mma.sync m16n8k16), cp.async double-buffered,
// fragment loads via ldmatrix.x4 (6 load issues per k-step instead of 24).
// C[M,N] = A[M,K] * B[N,K]^T, fp32 accumulate.
// smem row stride 72 halves (144 B): ldmatrix 8-row groups hit disjoint
// bank quartets (36 words == 4 mod 32).
// ---------------------------------------------------------------------------
template<int BM, int BN, int BK, int WM, int WN,
         bool BIAS, bool RELU, bool RESID, bool OUTH>
__global__ __launch_bounds__((BM/WM)*(BN/WN)*32) void hgemm_kernel(
    const __half* __restrict__ A, const __half* __restrict__ Bm,
    const float* __restrict__ bias, const float* __restrict__ resid,
    void* __restrict__ Cv, int Kdim, int lda, int ldb, int ldc)
{
    constexpr int WARPS_M = BM / WM;
    constexpr int WARPS_N = BN / WN;
    constexpr int THREADS = WARPS_M * WARPS_N * 32;
    constexpr int MT  = WM / 16;
    constexpr int NTL = WN / 8;
    constexpr int KS  = BK / 16;
    constexpr int AS  = BK + 8;            // half stride (72)
    constexpr int A_TILE = BM * AS;        // halves
    constexpr int B_TILE = BN * AS;

    extern __shared__ __half hsm[];
    __half* As_base = hsm;
    __half* Bs_base = hsm + 2 * A_TILE;

    const int tid  = threadIdx.x;
    const int warp = tid >> 5;
    const int lane = tid & 31;
    const int g  = lane >> 2;
    const int tg = lane & 3;
    const int warp_m = warp / WARPS_N;
    const int warp_n = warp % WARPS_N;

    const int block_m = blockIdx.y * BM;
    const int block_n = blockIdx.x * BN;

    const uint32_t sA0 = smem_u32(As_base);
    const uint32_t sB0 = smem_u32(Bs_base);

    // ldmatrix lane maps:
    // A (16x16 per mt): row = (l&7)+((l>>3)&1)*8, colblock = l>>4
    const int arow = (lane & 7) + (((lane >> 3) & 1) << 3);
    const int acb  = lane >> 4;
    // B (two 8-row nt per x4): row = (l&7)+(l>>4)*8, colblock = (l>>3)&1
    const int brow = (lane & 7) + ((lane >> 4) << 3);
    const int bcb  = (lane >> 3) & 1;
    const uint32_t aLane = (uint32_t)((warp_m * WM + arow) * AS + acb * 8) * 2u;
    const uint32_t bLane = (uint32_t)((warp_n * WN + brow) * AS + bcb * 8) * 2u;

    float acc[MT][NTL][4];
    #pragma unroll
    for (int i = 0; i < MT; i++)
        #pragma unroll
        for (int j = 0; j < NTL; j++)
            #pragma unroll
            for (int r = 0; r < 4; r++) acc[i][j][r] = 0.f;

    auto load_tile = [&](int k0, int st) {
        constexpr int A_IT = (BM * BK / 8) / THREADS;
        #pragma unroll
        for (int i = 0; i < A_IT; i++) {
            const int idx = tid + i * THREADS;
            const int r = idx / (BK / 8), c = idx % (BK / 8);
            cp16(sA0 + (uint32_t)(st * A_TILE + r * AS + c * 8) * 2u,
                 &A[(size_t)(block_m + r) * lda + k0 + c * 8]);
        }
        constexpr int B_IT = (BN * BK / 8) / THREADS;
        #pragma unroll
        for (int i = 0; i < B_IT; i++) {
            const int idx = tid + i * THREADS;
            const int r = idx / (BK / 8), c = idx % (BK / 8);
            cp16(sB0 + (uint32_t)(st * B_TILE + r * AS + c * 8) * 2u,
                 &Bm[(size_t)(block_n + r) * ldb + k0 + c * 8]);
        }
    };

    const int KT = Kdim / BK;
    load_tile(0, 0);
    cp_commit();

    for (int kt = 0; kt < KT; kt++) {
        if (kt + 1 < KT) {
            load_tile((kt + 1) * BK, (kt + 1) & 1);
            cp_commit();
            cp_wait<1>();
        } else {
            cp_wait<0>();
        }
        __syncthreads();

        const uint32_t sAst = sA0 + (uint32_t)((kt & 1) * A_TILE) * 2u;
        const uint32_t sBst = sB0 + (uint32_t)((kt & 1) * B_TILE) * 2u;

        #pragma unroll
        for (int ks = 0; ks < KS; ks++) {
            const uint32_t kboff = (uint32_t)(ks * 16) * 2u;
            uint32_t af[MT][4];
            uint32_t bf[NTL][2];
            #pragma unroll
            for (int mt = 0; mt < MT; mt++) {
                ldm_x4(af[mt][0], af[mt][1], af[mt][2], af[mt][3],
                       sAst + aLane + (uint32_t)(mt * 16 * AS) * 2u + kboff);
            }
            #pragma unroll
            for (int p = 0; p < NTL / 2; p++) {
                uint32_t d0, d1, d2, d3;
                ldm_x4(d0, d1, d2, d3,
                       sBst + bLane + (uint32_t)(p * 16 * AS) * 2u + kboff);
                bf[2*p][0] = d0; bf[2*p][1] = d1;
                bf[2*p+1][0] = d2; bf[2*p+1][1] = d3;
            }
            #pragma unroll
            for (int mt = 0; mt < MT; mt++)
                #pragma unroll
                for (int nt = 0; nt < NTL; nt++)
                    mma_f16(acc[mt][nt], af[mt], bf[nt]);
        }
        __syncthreads();
    }

    // --- epilogue ---
    #pragma unroll
    for (int mt = 0; mt < MT; mt++) {
        const int row0 = block_m + warp_m * WM + mt * 16 + g;
        #pragma unroll
        for (int nt = 0; nt < NTL; nt++) {
            const int col = block_n + warp_n * WN + nt * 8 + 2 * tg;
            float2 lo = make_float2(acc[mt][nt][0], acc[mt][nt][1]);
            float2 hi = make_float2(acc[mt][nt][2], acc[mt][nt][3]);
            if (BIAS) {
                const float2 bb = *(const float2*)&bias[col];
                lo.x += bb.x; lo.y += bb.y; hi.x += bb.x; hi.y += bb.y;
            }
            if (RELU) {
                lo.x = fmaxf(lo.x, 0.f); lo.y = fmaxf(lo.y, 0.f);
                hi.x = fmaxf(hi.x, 0.f); hi.y = fmaxf(hi.y, 0.f);
            }
            if (RESID) {
                const float2 r0 = *(const float2*)&resid[(size_t)row0 * ldc + col];
                const float2 r1 = *(const float2*)&resid[(size_t)(row0 + 8) * ldc + col];
                lo.x += r0.x; lo.y += r0.y; hi.x += r1.x; hi.y += r1.y;
            }
            if (OUTH) {
                __half* C = (__half*)Cv;
                *(half2*)&C[(size_t)row0 * ldc + col]       = __floats2half2_rn(lo.x, lo.y);
                *(half2*)&C[(size_t)(row0 + 8) * ldc + col] = __floats2half2_rn(hi.x, hi.y);
            } else {
                float* C = (float*)Cv;
                *(float2*)&C[(size_t)row0 * ldc + col]       = lo;
                *(float2*)&C[(size_t)(row0 + 8) * ldc + col] = hi;
            }
        }
    }
}

// ---------------------------------------------------------------------------
// Host-side launch pipeline (graph-capturable: kernel launches only)
// ---------------------------------------------------------------------------
extern "C" void kernel_launch(void* const* d_in, const int* in_sizes, int n_in,
                              void* d_out, int out_size)
{
    const float* x      = (const float*)d_in[0];
    const int*   mask   = (const int*)  d_in[1];
    const float* wq     = (const float*)d_in[2];
    const float* wk     = (const float*)d_in[3];
    const float* wv     = (const float*)d_in[4];
    const float* wo     = (const float*)d_in[5];
    const float* w1     = (const float*)d_in[6];
    const float* b1     = (const float*)d_in[7];
    const float* w2     = (const float*)d_in[8];
    const float* b2     = (const float*)d_in[9];
    const float* alpha1 = (const float*)d_in[10];
    const float* bias1  = (const float*)d_in[11];
    const float* alpha2 = (const float*)d_in[12];
    const float* bias2  = (const float*)d_in[13];
    float* out = (float*)d_out;

    __half *xnh, *xn2h, *avh, *hh, *qkvh, *wqkvh, *worh, *w1h, *w2h;
    float *x1;
    cudaGetSymbolAddress((void**)&xnh,   g_xnh);
    cudaGetSymbolAddress((void**)&xn2h,  g_xn2h);
    cudaGetSymbolAddress((void**)&avh,   g_avh);
    cudaGetSymbolAddress((void**)&hh,    g_hh);
    cudaGetSymbolAddress((void**)&qkvh,  g_qkvh);
    cudaGetSymbolAddress((void**)&x1,    g_x1);
    cudaGetSymbolAddress((void**)&wqkvh, g_wqkvh);
    cudaGetSymbolAddress((void**)&worh,  g_worh);
    cudaGetSymbolAddress((void**)&w1h,   g_w1h);
    cudaGetSymbolAddress((void**)&w2h,   g_w2h);

    // smem sizes
    constexpr int SMEM_H     = 2 * (128 * 72 + 128 * 72) * 2;              // 73728 B
    constexpr int SMEM_FLASH = (2 * 64 * 72 * 2) * 2 + 2 * 64 * 4;         // 37376 B

    cudaFuncSetAttribute(hgemm_kernel<128,128,64,64,32,false,false,false,true>,
                         cudaFuncAttributeMaxDynamicSharedMemorySize, SMEM_H);
    cudaFuncSetAttribute(hgemm_kernel<128,128,64,64,32,false,false,true,false>,
                         cudaFuncAttributeMaxDynamicSharedMemorySize, SMEM_H);
    cudaFuncSetAttribute(hgemm_kernel<128,128,64,64,32,true,true,false,true>,
                         cudaFuncAttributeMaxDynamicSharedMemorySize, SMEM_H);
    cudaFuncSetAttribute(hgemm_kernel<128,128,64,64,32,true,false,true,false>,
                         cudaFuncAttributeMaxDynamicSharedMemorySize, SMEM_H);
    cudaFuncSetAttribute(flash_kernel,
                         cudaFuncAttributeMaxDynamicSharedMemorySize, SMEM_FLASH);

    // 0) weights -> fp16, one merged launch (wq/wk/wv into concatenated buffer)
    round_all_kernel<<<3072, 256>>>(
        (const float4*)wq, (const float4*)wk, (const float4*)wv,
        (const float4*)wo, (const float4*)w1, (const float4*)w2,
        wqkvh, worh, w1h, w2h);

    // 1) LN1 -> fp16
    ln_kernel<<<cROWS, 256>>>(x, alpha1, bias1, xnh);

    // 2) Fused QKV projection: [4096,1024] x [3072,1024]^T -> fp16
    {
        dim3 grid(c3D / 128, cROWS / 128);
        hgemm_kernel<128,128,64,64,32,false,false,false,true><<<grid, 256, SMEM_H>>>(
            xnh, wqkvh, nullptr, nullptr, qkvh, cD, cD, cD, c3D);
    }

    // 3) Flash attention -> av (fp16)
    {
        dim3 fgrid(cS / 128, cB * cH);
        flash_kernel<<<fgrid, 256, SMEM_FLASH>>>(qkvh, mask, avh);
    }

    // 4) WO projection + residual: x1 = x + av @ wo^T (fp32 out)
    {
        dim3 grid(cD / 128, cROWS / 128);
        hgemm_kernel<128,128,64,64,32,false,false,true,false><<<grid, 256, SMEM_H>>>(
            avh, worh, nullptr, x, x1, cD, cD, cD, cD);
    }

    // 5) LN2 -> fp16
    ln_kernel<<<cROWS, 256>>>(x1, alpha2, bias2, xn2h);

    // 6) FFN1: h = relu(xn2 @ w1^T + b1) -> fp16
    {
        dim3 grid(cDFF / 128, cROWS / 128);
        hgemm_kernel<128,128,64,64,32,true,true,false,true><<<grid, 256, SMEM_H>>>(
            xn2h, w1h, b1, nullptr, hh, cD, cD, cD, cDFF);
    }

    // 7) FFN2: out = x1 + h @ w2^T + b2 (fp32 out)
    {
        dim3 grid(cD / 128, cROWS / 128);
        hgemm_kernel<128,128,64,64,32,true,false,true,false><<<grid, 256, SMEM_H>>>(
            hh, w2h, b2, x1, out, cDFF, cDFF, cDFF, cD);
    }
    (void)in_sizes; (void)n_in; (void)out_size;
}